// round 11
// baseline (speedup 1.0000x reference)
#include <cuda_runtime.h>
#include <math.h>

#define NB 2
#define RR 360
#define RRH 180
#define NN 100
#define SS 200
#define KXN 101
#define NPIX (NN*NN)
#define NLIGH (NB*RRH*2)          // 720 forward-transformed ligand images
#define NIMGH (NLIGH + NB*2)      // +4 receptor images = 724
#define GPITCH 102

// ---------------- scratch (device globals; no allocation allowed) ----------
__device__ float  d_h1[4][9][NPIX];
__device__ float  d_feat[4][2][NPIX];            // 0..1 receptor b, 2..3 ligand b
__device__ float2 d_G[NIMGH][NN][GPITCH];        // row DFT: [img][y][kx]
__device__ float2 d_F[NIMGH][KXN][SS];           // fwd spectrum: [img][kx][ky]
__device__ float2 d_H[NB*RR][KXN][SS];           // after inv-ky: [imgH][kx][y]
__device__ unsigned int d_best[NB];
__device__ float  d_pos[NB];

// e^{i pi j/4}: cos, sin tables (exact-to-eps reseed points)
__device__ __constant__ float C8[8] = {1.f, 0.70710678118654752f, 0.f, -0.70710678118654752f,
                                       -1.f, -0.70710678118654752f, 0.f, 0.70710678118654752f};
__device__ __constant__ float S8[8] = {0.f, 0.70710678118654752f, 1.f, 0.70710678118654752f,
                                       0.f, -0.70710678118654752f, -1.f, -0.70710678118654752f};

__device__ __forceinline__ unsigned fenc(float f) {
    unsigned u = __float_as_uint(f);
    return (u & 0x80000000u) ? ~u : (u | 0x80000000u);
}
__device__ __forceinline__ float fdec(unsigned e) {
    unsigned u = (e & 0x80000000u) ? (e & 0x7FFFFFFFu) : ~e;
    return __uint_as_float(u);
}

__global__ void k_init() {
    int t = threadIdx.x;
    if (t < NB) { d_best[t] = 0u; d_pos[t] = 0.0f; }
}

// ---------------- conv1 + norm_relu (FIELDS1) -------------------------------
__global__ void k_conv1(const float* __restrict__ rec, const float* __restrict__ lig,
                        const float* __restrict__ w1) {
    int img = blockIdx.y;
    int p = blockIdx.x * blockDim.x + threadIdx.x;
    if (p >= NPIX) return;
    int y = p / NN, x = p % NN;
    const float* src = (img < NB) ? (rec + img * NPIX) : (lig + (img - NB) * NPIX);
    float acc[9];
#pragma unroll
    for (int o = 0; o < 9; o++) acc[o] = 0.0f;
#pragma unroll
    for (int ky = 0; ky < 5; ky++) {
        int iy = y + ky - 2;
        if ((unsigned)iy >= NN) continue;
#pragma unroll
        for (int kx = 0; kx < 5; kx++) {
            int ix = x + kx - 2;
            if ((unsigned)ix >= NN) continue;
            float v = __ldg(src + iy * NN + ix);
#pragma unroll
            for (int o = 0; o < 9; o++)
                acc[o] = fmaf(v, __ldg(w1 + o * 25 + ky * 5 + kx), acc[o]);
        }
    }
    {
        float a = acc[0];
        float n = sqrtf(a * a + 1e-12f);
        d_h1[img][0][p] = a * (n / (n + 1e-12f));
    }
#pragma unroll
    for (int g = 0; g < 4; g++) {
        int s = 1 + 2 * g;
        float a = acc[s], b = acc[s + 1];
        float n = sqrtf(a * a + b * b + 1e-12f);
        float sc = n / (n + 1e-12f);
        d_h1[img][s][p] = a * sc;
        d_h1[img][s + 1][p] = b * sc;
    }
}

// ---------------- conv2 + norm_relu (FIELDS2) + features --------------------
__global__ void k_conv2(const float* __restrict__ w2) {
    int img = blockIdx.y;
    int p = blockIdx.x * blockDim.x + threadIdx.x;
    if (p >= NPIX) return;
    int y = p / NN, x = p % NN;
    float acc[3] = {0.f, 0.f, 0.f};
    for (int ci = 0; ci < 9; ci++) {
        const float* hp = d_h1[img][ci];
#pragma unroll
        for (int ky = 0; ky < 5; ky++) {
            int iy = y + ky - 2;
            if ((unsigned)iy >= NN) continue;
#pragma unroll
            for (int kx = 0; kx < 5; kx++) {
                int ix = x + kx - 2;
                if ((unsigned)ix >= NN) continue;
                float v = hp[iy * NN + ix];
#pragma unroll
                for (int o = 0; o < 3; o++)
                    acc[o] = fmaf(v, __ldg(w2 + ((o * 9 + ci) * 5 + ky) * 5 + kx), acc[o]);
            }
        }
    }
    float o0, o1, o2;
    {
        float a = acc[0];
        float n = sqrtf(a * a + 1e-12f);
        o0 = a * (n / (n + 1e-12f));
    }
    {
        float a = acc[1], b = acc[2];
        float n = sqrtf(a * a + b * b + 1e-12f);
        float sc = n / (n + 1e-12f);
        o1 = a * sc; o2 = b * sc;
    }
    d_feat[img][0][p] = fabsf(o0);
    d_feat[img][1][p] = sqrtf(o1 * o1 + o2 * o2 + 1e-12f);
}

__device__ __forceinline__ float samp(const float* __restrict__ im, float yf, float xf) {
    if (yf < 0.f || yf >= 100.f || xf < 0.f || xf >= 100.f) return 0.f;
    int yc = (int)yf, xc = (int)xf;
    return im[yc * NN + xc];
}

// ---------------- rotate (fused) + row DFT ----------------------------------
// Only rotations r = 0..179 computed; r+180 derived later via phase*conj.
__global__ void __launch_bounds__(256) k_rot_rowdft() {
    __shared__ __align__(16) float rotT[NN * 104];   // [x][y], pitch 104
    int bid = blockIdx.x;
    int tid = threadIdx.x;
    const float* src;
    bool ident;
    float ct = 1.f, st = 0.f;
    if (bid < NLIGH) {
        int c = bid & 1;
        int r = (bid >> 1) % RRH;
        int b = bid / (2 * RRH);
        src = d_feat[NB + b][c];
        double th = -3.14159265358979323846 + (double)r * (6.283185307179586477 / 360.0);
        ct = (float)cos(th); st = (float)sin(th);
        ident = false;
    } else {
        int i = bid - NLIGH;
        src = d_feat[i >> 1][i & 1];
        ident = true;
    }
    for (int p = tid; p < NPIX; p += blockDim.x) {
        int i = p / NN, j = p % NN;
        float val;
        if (ident) {
            val = src[p];
        } else {
            float xs = (float)j - 49.5f, ys = (float)i - 49.5f;
            float xq = ct * xs + st * ys + 49.5f;
            float yq = -st * xs + ct * ys + 49.5f;
            float x0f = floorf(xq), y0f = floorf(yq);
            float wx = xq - x0f, wy = yq - y0f;
            val = samp(src, y0f, x0f) * (1.f - wy) * (1.f - wx)
                + samp(src, y0f, x0f + 1.f) * (1.f - wy) * wx
                + samp(src, y0f + 1.f, x0f) * wy * (1.f - wx)
                + samp(src, y0f + 1.f, x0f + 1.f) * wy * wx;
        }
        rotT[j * 104 + i] = val;   // transposed store
    }
    __syncthreads();
    for (int task = tid; task < 5 * KXN; task += 256) {
        int kx = task % KXN;
        int y0 = (task / KXN) * 20;
        float sif, srf;
        sincosf(-3.14159265358979f * (float)kx * 0.01f, &sif, &srf);  // step e^{-i pi kx/100}
        float wr = 1.f, wi = 0.f;
        float aR[20], aI[20];
#pragma unroll
        for (int i = 0; i < 20; i++) { aR[i] = 0.f; aI[i] = 0.f; }
        for (int x = 0; x < NN; x++) {
            if ((x & 24) && (x % 25 == 0)) {      // x = 25, 50, 75: exact reseed
                int j = (kx * (x / 25)) & 7;      // phase = -pi*j/4
                wr = C8[j]; wi = -S8[j];
            }
            const float4* rp = reinterpret_cast<const float4*>(&rotT[x * 104 + y0]);
#pragma unroll
            for (int q = 0; q < 5; q++) {
                float4 v = rp[q];
                aR[q*4+0] = fmaf(v.x, wr, aR[q*4+0]); aI[q*4+0] = fmaf(v.x, wi, aI[q*4+0]);
                aR[q*4+1] = fmaf(v.y, wr, aR[q*4+1]); aI[q*4+1] = fmaf(v.y, wi, aI[q*4+1]);
                aR[q*4+2] = fmaf(v.z, wr, aR[q*4+2]); aI[q*4+2] = fmaf(v.z, wi, aI[q*4+2]);
                aR[q*4+3] = fmaf(v.w, wr, aR[q*4+3]); aI[q*4+3] = fmaf(v.w, wi, aI[q*4+3]);
            }
            float nr = fmaf(wr, srf, -wi * sif);
            float ni = fmaf(wr, sif, wi * srf);
            wr = nr; wi = ni;
        }
#pragma unroll
        for (int i = 0; i < 20; i++)
            d_G[bid][y0 + i][kx] = make_float2(aR[i], aI[i]);
    }
}

// Complex accumulate 2 complex vals (float4) with explicit twiddle
#define CACC4(Tr, Ti, f4, twr, twi) \
    Tr[2*q]   = fmaf((f4).x, twr, Tr[2*q]);   Tr[2*q]   = fmaf(-(f4).y, twi, Tr[2*q]); \
    Ti[2*q]   = fmaf((f4).x, twi, Ti[2*q]);   Ti[2*q]   = fmaf( (f4).y, twr, Ti[2*q]); \
    Tr[2*q+1] = fmaf((f4).z, twr, Tr[2*q+1]); Tr[2*q+1] = fmaf(-(f4).w, twi, Tr[2*q+1]); \
    Ti[2*q+1] = fmaf((f4).z, twi, Ti[2*q+1]); Ti[2*q+1] = fmaf( (f4).w, twr, Ti[2*q+1]);

// Real accumulate Re(H * tw) for 2 complex vals (twiddle carries any weight)
#define RACC4(E, f4, twr, twi) \
    E[2*q]   = fmaf((f4).x, twr, E[2*q]);   E[2*q]   = fmaf(-(f4).y, twi, E[2*q]); \
    E[2*q+1] = fmaf((f4).z, twr, E[2*q+1]); E[2*q+1] = fmaf(-(f4).w, twi, E[2*q+1]);

// ---------------- column DFT, RADIX-4 (input y = 4s+c, output ky = u+50j) ---
// F[u+50j] = T0 + (-i)^j T1 + (-1)^j T2 + i^j T3,  Tc = sum_s G[4s+c] w^{4s+c},
// w = e^{-i pi u/100}.
__global__ void __launch_bounds__(256) k_coldft() {
    __shared__ __align__(16) float2 GT[NN][56];   // [y][kx-local]
    int img = blockIdx.x >> 1;
    int half = blockIdx.x & 1;
    int kxg0 = half * 52;
    int width = half ? 49 : 52;
    int tid = threadIdx.x;
    for (int t = tid; t < NN * 56; t += 256) {
        int y = t / 56, kxl = t % 56;
        GT[y][kxl] = (kxl < width) ? d_G[img][y][kxg0 + kxl] : make_float2(0.f, 0.f);
    }
    __syncthreads();
    // 650 tasks = 13 kx-groups of 4 x 50 u (u fastest)
    for (int task = tid; task < 650; task += 256) {
        int u = task % 50;
        int kxl0 = (task / 50) * 4;
        float wbr, wbi;
        sincosf(-3.14159265358979f * (float)u * 0.01f, &wbi, &wbr);     // w
        float w2br = wbr * wbr - wbi * wbi,  w2bi = 2.f * wbr * wbi;    // w^2
        float w3br = w2br * wbr - w2bi * wbi, w3bi = w2br * wbi + w2bi * wbr; // w^3
        int uww = (u > 25) ? u - 50 : u;
        float Wr, Wi;
        sincosf(-6.28318530717959f * (float)uww * 0.02f, &Wi, &Wr);     // W = w^4
        float wsr = 1.f, wsi = 0.f;                                     // w^{4s}
        float T0r[4], T0i[4], T1r[4], T1i[4], T2r[4], T2i[4], T3r[4], T3i[4];
#pragma unroll
        for (int j = 0; j < 4; j++) { T0r[j]=T0i[j]=T1r[j]=T1i[j]=T2r[j]=T2i[j]=T3r[j]=T3i[j]=0.f; }
        for (int s = 0; s < 25; s++) {
            float w1r = wsr * wbr - wsi * wbi,   w1i = wsr * wbi + wsi * wbr;
            float w2r = wsr * w2br - wsi * w2bi, w2i = wsr * w2bi + wsi * w2br;
            float w3r = wsr * w3br - wsi * w3bi, w3i = wsr * w3bi + wsi * w3br;
            const float4* p0 = reinterpret_cast<const float4*>(&GT[4*s    ][kxl0]);
            const float4* p1 = reinterpret_cast<const float4*>(&GT[4*s + 1][kxl0]);
            const float4* p2 = reinterpret_cast<const float4*>(&GT[4*s + 2][kxl0]);
            const float4* p3 = reinterpret_cast<const float4*>(&GT[4*s + 3][kxl0]);
#pragma unroll
            for (int q = 0; q < 2; q++) {
                float4 e0 = p0[q]; CACC4(T0r, T0i, e0, wsr, wsi)
                float4 e1 = p1[q]; CACC4(T1r, T1i, e1, w1r, w1i)
                float4 e2 = p2[q]; CACC4(T2r, T2i, e2, w2r, w2i)
                float4 e3 = p3[q]; CACC4(T3r, T3i, e3, w3r, w3i)
            }
            float nsr = wsr * Wr - wsi * Wi;
            float nsi = wsr * Wi + wsi * Wr;
            wsr = nsr; wsi = nsi;
        }
#pragma unroll
        for (int j = 0; j < 4; j++) {
            int kxl = kxl0 + j;
            if (kxl >= width) continue;
            int kx = kxg0 + kxl;
            float acr = T0r[j] + T2r[j], aci = T0i[j] + T2i[j];
            float amr = T0r[j] - T2r[j], ami = T0i[j] - T2i[j];
            float bdr = T1r[j] + T3r[j], bdi = T1i[j] + T3i[j];
            float bmr = T1r[j] - T3r[j], bmi = T1i[j] - T3i[j];
            d_F[img][kx][u]       = make_float2(acr + bdr, aci + bdi);
            d_F[img][kx][u + 100] = make_float2(acr - bdr, aci - bdi);
            // j=1: T0 - iT1 - T2 + iT3 = (am) - i(bm)
            d_F[img][kx][u + 50]  = make_float2(amr + bmi, ami - bmr);
            // j=3: T0 + iT1 - T2 - iT3 = (am) + i(bm)
            d_F[img][kx][u + 150] = make_float2(amr - bmi, ami + bmr);
        }
    }
}

// ---------------- combine spectra + inverse ky (RADIX-4 output split) -------
#define CACC(Sr, Si, f4) \
    Sr[2*q]   = fmaf((f4).x, wr, Sr[2*q]);   Sr[2*q]   = fmaf(-(f4).y, wi, Sr[2*q]); \
    Si[2*q]   = fmaf((f4).x, wi, Si[2*q]);   Si[2*q]   = fmaf( (f4).y, wr, Si[2*q]); \
    Sr[2*q+1] = fmaf((f4).z, wr, Sr[2*q+1]); Sr[2*q+1] = fmaf(-(f4).w, wi, Sr[2*q+1]); \
    Si[2*q+1] = fmaf((f4).z, wi, Si[2*q+1]); Si[2*q+1] = fmaf( (f4).w, wr, Si[2*q+1]);

__global__ void __launch_bounds__(320) k_combine_invy(const float* __restrict__ wb,
        const float* __restrict__ wc1, const float* __restrict__ wc2,
        const float* __restrict__ wk) {
    __shared__ __align__(16) float2 sfs[SS][24];
    __shared__ float2 ph[304];
    int chunk = blockIdx.x % 5;
    int imgH = blockIdx.x / 5;
    int b = imgH / RR;
    int r = imgH % RR;
    bool flip = (r >= RRH);
    int rb180 = flip ? r - RRH : r;
    int kxg0 = chunk * 24;
    int width = (KXN - kxg0 < 24) ? (KXN - kxg0) : 24;
    int tid = threadIdx.x;
    float w0 = *wb, w1v = *wc1, w2v = *wc2, w3 = *wk;
    int imgL0 = (b * RRH + rb180) * 2, imgL1 = imgL0 + 1;
    int imgR0 = NLIGH + b * 2, imgR1 = imgR0 + 1;
    if (flip) {
        for (int s = tid; s < 301; s += 320) {
            float pr, pi_;
            sincosf(3.14159265358979f * 0.01f * (float)s, &pi_, &pr);
            if (s & 1) { pr = -pr; pi_ = -pi_; }
            ph[s] = make_float2(pr, pi_);
        }
        __syncthreads();
    }
    for (int e = tid; e < SS * 24; e += 320) {
        int ky = e % SS, kxl = e / SS;
        float2 v = make_float2(0.f, 0.f);
        if (kxl < width) {
            int kx = kxg0 + kxl;
            float2 lb = d_F[imgL0][kx][ky];
            float2 lB = d_F[imgL1][kx][ky];
            if (flip) {
                float2 p = ph[kx + ky];
                float t;
                t    = p.x * lb.x + p.y * lb.y;
                lb.y = p.y * lb.x - p.x * lb.y;
                lb.x = t;
                t    = p.x * lB.x + p.y * lB.y;
                lB.y = p.y * lB.x - p.x * lB.y;
                lB.x = t;
            }
            float2 rb = d_F[imgR0][kx][ky];
            float2 rB = d_F[imgR1][kx][ky];
            float ur = w0 * lb.x + w1v * lB.x, ui = w0 * lb.y + w1v * lB.y;
            float vr = w2v * lb.x - w3 * lB.x, vi = w2v * lb.y - w3 * lB.y;
            v.x = rb.x * ur + rb.y * ui + rB.x * vr + rB.y * vi;
            v.y = rb.x * ui - rb.y * ur + rB.x * vi - rB.y * vr;
        }
        sfs[ky][kxl] = v;
    }
    __syncthreads();
    for (int task = tid; task < 300; task += 320) {
        int v = task % 50;
        int kxl0 = (task / 50) * 4;
        int vw = (v > 25) ? v - 50 : v;
        float sif, srf;
        sincosf(6.28318530717959f * (float)vw * 0.02f, &sif, &srf);  // step e^{2pi i v/50}
        float wr = 1.f, wi = 0.f;
        float S0r[4], S0i[4], S1r[4], S1i[4], S2r[4], S2i[4], S3r[4], S3i[4];
#pragma unroll
        for (int j = 0; j < 4; j++) { S0r[j]=S0i[j]=S1r[j]=S1i[j]=S2r[j]=S2i[j]=S3r[j]=S3i[j]=0.f; }
        for (int t = 0; t < 50; t++) {
            if (t == 25) {                          // phase = pi*v exact
                wr = (v & 1) ? -1.f : 1.f; wi = 0.f;
            }
            const float4* p0 = reinterpret_cast<const float4*>(&sfs[4*t    ][kxl0]);
            const float4* p1 = reinterpret_cast<const float4*>(&sfs[4*t + 1][kxl0]);
            const float4* p2 = reinterpret_cast<const float4*>(&sfs[4*t + 2][kxl0]);
            const float4* p3 = reinterpret_cast<const float4*>(&sfs[4*t + 3][kxl0]);
#pragma unroll
            for (int q = 0; q < 2; q++) {
                float4 e0 = p0[q]; CACC(S0r, S0i, e0)
                float4 e1 = p1[q]; CACC(S1r, S1i, e1)
                float4 e2 = p2[q]; CACC(S2r, S2i, e2)
                float4 e3 = p3[q]; CACC(S3r, S3i, e3)
            }
            float nr = fmaf(wr, srf, -wi * sif);
            float ni = fmaf(wr, sif, wi * srf);
            wr = nr; wi = ni;
        }
        float tr, ti;
        sincosf(3.14159265358979f * 0.01f * (float)v, &ti, &tr);   // t_v = e^{i pi v/100}
        float t2r = tr * tr - ti * ti, t2i = 2.f * tr * ti;
        float t3r = t2r * tr - t2i * ti, t3i = t2r * ti + t2i * tr;
#pragma unroll
        for (int j = 0; j < 4; j++) {
            int kxl = kxl0 + j;
            if (kxl >= width) continue;
            int kx = kxg0 + kxl;
            float ar = S0r[j], ai = S0i[j];
            float br = tr * S1r[j] - ti * S1i[j],   bi = tr * S1i[j] + ti * S1r[j];
            float cr = t2r * S2r[j] - t2i * S2i[j], ci = t2r * S2i[j] + t2i * S2r[j];
            float dr = t3r * S3r[j] - t3i * S3i[j], di = t3r * S3i[j] + t3i * S3r[j];
            float acr = ar + cr, aci = ai + ci;
            float amr = ar - cr, ami = ai - ci;
            float bdr = br + dr, bdi = bi + di;
            float bmr = br - dr, bmi = bi - di;
            d_H[imgH][kx][v]       = make_float2(acr + bdr, aci + bdi);
            d_H[imgH][kx][v + 100] = make_float2(acr - bdr, aci - bdi);
            d_H[imgH][kx][v + 50]  = make_float2(amr - bmi, ami + bmr);
            d_H[imgH][kx][v + 150] = make_float2(amr + bmi, ami - bmr);
        }
    }
}

// ---------------- inverse kx (real, RADIX-4 output split) + reduce ----------
// x = v+50j. kx mod 4: c=0 -> E0 (real, all j), c=2 -> E2 (real, sign (-1)^j),
// c=1 -> C1 (complex), c=3 -> C3 (complex). w = e^{2pi i v/200}.
// s[v]     = E0+E2+2(C1r+C3r);   s[v+50]  = E0-E2+2(C3i-C1i)
// s[v+100] = E0+E2-2(C1r+C3r);   s[v+150] = E0-E2+2(C1i-C3i)
__global__ void __launch_bounds__(256) k_invx_reduce(const int* __restrict__ gtr,
                                                     const int* __restrict__ gtt) {
    __shared__ __align__(16) float2 HT[KXN][20];
    __shared__ float red[256];
    int yc = blockIdx.x % 10;
    int imgH = blockIdx.x / 10;
    int b = imgH / RR, r = imgH % RR;
    int ybase = yc * 20;
    int tid = threadIdx.x;
    for (int e = tid; e < KXN * 20; e += 256) {
        int kx = e / 20, yl = e % 20;
        HT[kx][yl] = d_H[imgH][kx][ybase + yl];
    }
    __syncthreads();
    int gr = gtr[b], t0 = gtt[2 * b], t1 = gtt[2 * b + 1];
    const float inv = 1.0f / 40000.0f;
    float lmax = -3.4e38f;
    // 250 tasks = 5 y-groups of 4 x 50 v (v fastest)
    for (int task = tid; task < 250; task += 256) {
        int v = task % 50;
        int y0 = (task / 50) * 4;
        float wbr, wbi;
        sincosf(3.14159265358979f * (float)v * 0.01f, &wbi, &wbr);      // w = e^{i pi v/100}
        float w2br = wbr * wbr - wbi * wbi,  w2bi = 2.f * wbr * wbi;
        float w3br = w2br * wbr - w2bi * wbi, w3bi = w2br * wbi + w2bi * wbr;
        int vw = (v > 25) ? v - 50 : v;
        float Wr, Wi;
        sincosf(6.28318530717959f * (float)vw * 0.02f, &Wi, &Wr);       // W = w^4
        float wsr = 1.f, wsi = 0.f;                                     // w^{4t}
        float E0[4], E2[4], C1r[4], C1i[4], C3r[4], C3i[4];
        float sgn = (v & 1) ? -1.f : 1.f;
#pragma unroll
        for (int i = 0; i < 4; i++) {
            E0[i]  = HT[0][y0 + i].x + sgn * HT[100][y0 + i].x;
            E2[i]  = 0.f;
            C1r[i] = 0.f; C1i[i] = 0.f; C3r[i] = 0.f; C3i[i] = 0.f;
        }
        for (int t = 0; t < 25; t++) {
            float w1r = wsr * wbr - wsi * wbi,   w1i = wsr * wbi + wsi * wbr;   // w^{4t+1}
            float w2r = wsr * w2br - wsi * w2bi, w2i = wsr * w2bi + wsi * w2br; // w^{4t+2}
            float w3r = wsr * w3br - wsi * w3bi, w3i = wsr * w3bi + wsi * w3br; // w^{4t+3}
            float wnr = wsr * Wr - wsi * Wi,     wni = wsr * Wi + wsi * Wr;     // w^{4t+4}
            float e2r = 2.f * w2r, e2i = 2.f * w2i;
            float e0r = 2.f * wnr, e0i = 2.f * wni;
            const float4* p1 = reinterpret_cast<const float4*>(&HT[4*t + 1][y0]);
            const float4* p2 = reinterpret_cast<const float4*>(&HT[4*t + 2][y0]);
            const float4* p3 = reinterpret_cast<const float4*>(&HT[4*t + 3][y0]);
#pragma unroll
            for (int q = 0; q < 2; q++) {
                float4 h1 = p1[q]; CACC4(C1r, C1i, h1, w1r, w1i)
                float4 h2 = p2[q]; RACC4(E2, h2, e2r, e2i)
                float4 h3 = p3[q]; CACC4(C3r, C3i, h3, w3r, w3i)
            }
            if (t < 24) {
                const float4* p0 = reinterpret_cast<const float4*>(&HT[4*t + 4][y0]);
#pragma unroll
                for (int q = 0; q < 2; q++) {
                    float4 h0 = p0[q]; RACC4(E0, h0, e0r, e0i)
                }
            }
            wsr = wnr; wsi = wni;
        }
#pragma unroll
        for (int i = 0; i < 4; i++) {
            float e0 = E0[i], e2 = E2[i];
            float cr = 2.f * (C1r[i] + C3r[i]);
            float di = 2.f * (C3i[i] - C1i[i]);
            float s0 = (e0 + e2 + cr) * inv;    // x = v
            float s1 = (e0 - e2 + di) * inv;    // x = v+50
            float s2 = (e0 + e2 - cr) * inv;    // x = v+100
            float s3 = (e0 - e2 - di) * inv;    // x = v+150
            lmax = fmaxf(lmax, fmaxf(fmaxf(s0, s1), fmaxf(s2, s3)));
            int y = ybase + y0 + i;
            if (r == gr && y == t0) {
                if (v == t1)       d_pos[b] = s0;
                if (v + 50 == t1)  d_pos[b] = s1;
                if (v + 100 == t1) d_pos[b] = s2;
                if (v + 150 == t1) d_pos[b] = s3;
            }
        }
    }
    red[tid] = lmax;
    __syncthreads();
    for (int s2 = 128; s2 > 0; s2 >>= 1) {
        if (tid < s2) red[tid] = fmaxf(red[tid], red[tid + s2]);
        __syncthreads();
    }
    if (tid == 0) atomicMax(&d_best[b], fenc(red[0]));
}

__global__ void k_final(float* __restrict__ out) {
    if (threadIdx.x == 0) {
        float lp = 0.f, ln = 0.f;
        for (int b = 0; b < NB; b++) {
            float p = d_pos[b];
            lp += p + p * p;
            float m = fdec(d_best[b]);
            ln += -m + m * m;
        }
        out[0] = lp / (float)NB;
        out[1] = ln / (float)NB;
    }
}

extern "C" void kernel_launch(void* const* d_in, const int* in_sizes, int n_in,
                              void* d_out, int out_size) {
    const float* rec = (const float*)d_in[0];
    const float* lig = (const float*)d_in[1];
    const float* w1 = (const float*)d_in[2];
    const float* w2 = (const float*)d_in[3];
    const float* wb = (const float*)d_in[4];
    const float* wc1 = (const float*)d_in[5];
    const float* wc2 = (const float*)d_in[6];
    const float* wk = (const float*)d_in[7];
    const int* gtr = (const int*)d_in[8];
    const int* gtt = (const int*)d_in[9];
    float* out = (float*)d_out;

    k_init<<<1, 32>>>();
    dim3 gconv((NPIX + 255) / 256, 4);
    k_conv1<<<gconv, 256>>>(rec, lig, w1);
    k_conv2<<<gconv, 256>>>(w2);
    k_rot_rowdft<<<NIMGH, 256>>>();
    k_coldft<<<NIMGH * 2, 256>>>();
    k_combine_invy<<<NB * RR * 5, 320>>>(wb, wc1, wc2, wk);
    k_invx_reduce<<<NB * RR * 10, 256>>>(gtr, gtt);
    k_final<<<1, 32>>>(out);
}

// round 13
// speedup vs baseline: 1.6663x; 1.6663x over previous
#include <cuda_runtime.h>
#include <math.h>

#define NB 2
#define RR 360
#define RRH 180
#define NN 100
#define SS 200
#define KXN 101
#define NPIX (NN*NN)
#define NLIGH (NB*RRH*2)
#define NIMGH (NLIGH + NB*2)
#define GPITCH 102

__device__ float  d_h1[4][9][NPIX];
__device__ float  d_feat[4][2][NPIX];
__device__ float2 d_G[NIMGH][NN][GPITCH];
__device__ float2 d_F[NIMGH][KXN][SS];
__device__ float2 d_H[NB*RR][KXN][SS];
__device__ unsigned int d_best[NB];
__device__ float  d_pos[NB];

__device__ __constant__ float C8[8] = {1.f, 0.70710678118654752f, 0.f, -0.70710678118654752f,
                                       -1.f, -0.70710678118654752f, 0.f, 0.70710678118654752f};
__device__ __constant__ float S8[8] = {0.f, 0.70710678118654752f, 1.f, 0.70710678118654752f,
                                       0.f, -0.70710678118654752f, -1.f, -0.70710678118654752f};

__device__ __forceinline__ unsigned fenc(float f) {
    unsigned u = __float_as_uint(f);
    return (u & 0x80000000u) ? ~u : (u | 0x80000000u);
}
__device__ __forceinline__ float fdec(unsigned e) {
    unsigned u = (e & 0x80000000u) ? (e & 0x7FFFFFFFu) : ~e;
    return __uint_as_float(u);
}

__global__ void k_init() {
    int t = threadIdx.x;
    if (t < NB) { d_best[t] = 0u; d_pos[t] = 0.0f; }
}

// ---------------- conv1 + norm_relu (FIELDS1) -------------------------------
__global__ void k_conv1(const float* __restrict__ rec, const float* __restrict__ lig,
                        const float* __restrict__ w1) {
    int img = blockIdx.y;
    int p = blockIdx.x * blockDim.x + threadIdx.x;
    if (p >= NPIX) return;
    int y = p / NN, x = p % NN;
    const float* src = (img < NB) ? (rec + img * NPIX) : (lig + (img - NB) * NPIX);
    float acc[9];
#pragma unroll
    for (int o = 0; o < 9; o++) acc[o] = 0.0f;
#pragma unroll
    for (int ky = 0; ky < 5; ky++) {
        int iy = y + ky - 2;
        if ((unsigned)iy >= NN) continue;
#pragma unroll
        for (int kx = 0; kx < 5; kx++) {
            int ix = x + kx - 2;
            if ((unsigned)ix >= NN) continue;
            float v = __ldg(src + iy * NN + ix);
#pragma unroll
            for (int o = 0; o < 9; o++)
                acc[o] = fmaf(v, __ldg(w1 + o * 25 + ky * 5 + kx), acc[o]);
        }
    }
    {
        float a = acc[0];
        float n = sqrtf(a * a + 1e-12f);
        d_h1[img][0][p] = a * (n / (n + 1e-12f));
    }
#pragma unroll
    for (int g = 0; g < 4; g++) {
        int s = 1 + 2 * g;
        float a = acc[s], b = acc[s + 1];
        float n = sqrtf(a * a + b * b + 1e-12f);
        float sc = n / (n + 1e-12f);
        d_h1[img][s][p] = a * sc;
        d_h1[img][s + 1][p] = b * sc;
    }
}

// ---------------- conv2 + norm_relu (FIELDS2) + features --------------------
__global__ void k_conv2(const float* __restrict__ w2) {
    int img = blockIdx.y;
    int p = blockIdx.x * blockDim.x + threadIdx.x;
    if (p >= NPIX) return;
    int y = p / NN, x = p % NN;
    float acc[3] = {0.f, 0.f, 0.f};
    for (int ci = 0; ci < 9; ci++) {
        const float* hp = d_h1[img][ci];
#pragma unroll
        for (int ky = 0; ky < 5; ky++) {
            int iy = y + ky - 2;
            if ((unsigned)iy >= NN) continue;
#pragma unroll
            for (int kx = 0; kx < 5; kx++) {
                int ix = x + kx - 2;
                if ((unsigned)ix >= NN) continue;
                float v = hp[iy * NN + ix];
#pragma unroll
                for (int o = 0; o < 3; o++)
                    acc[o] = fmaf(v, __ldg(w2 + ((o * 9 + ci) * 5 + ky) * 5 + kx), acc[o]);
            }
        }
    }
    float o0, o1, o2;
    {
        float a = acc[0];
        float n = sqrtf(a * a + 1e-12f);
        o0 = a * (n / (n + 1e-12f));
    }
    {
        float a = acc[1], b = acc[2];
        float n = sqrtf(a * a + b * b + 1e-12f);
        float sc = n / (n + 1e-12f);
        o1 = a * sc; o2 = b * sc;
    }
    d_feat[img][0][p] = fabsf(o0);
    d_feat[img][1][p] = sqrtf(o1 * o1 + o2 * o2 + 1e-12f);
}

__device__ __forceinline__ float samp(const float* __restrict__ im, float yf, float xf) {
    if (yf < 0.f || yf >= 100.f || xf < 0.f || xf >= 100.f) return 0.f;
    int yc = (int)yf, xc = (int)xf;
    return im[yc * NN + xc];
}

// ---------------- rotate (fused) + row DFT ----------------------------------
__global__ void __launch_bounds__(256) k_rot_rowdft() {
    __shared__ __align__(16) float rotT[NN * 104];
    int bid = blockIdx.x;
    int tid = threadIdx.x;
    const float* src;
    bool ident;
    float ct = 1.f, st = 0.f;
    if (bid < NLIGH) {
        int c = bid & 1;
        int r = (bid >> 1) % RRH;
        int b = bid / (2 * RRH);
        src = d_feat[NB + b][c];
        double th = -3.14159265358979323846 + (double)r * (6.283185307179586477 / 360.0);
        ct = (float)cos(th); st = (float)sin(th);
        ident = false;
    } else {
        int i = bid - NLIGH;
        src = d_feat[i >> 1][i & 1];
        ident = true;
    }
    for (int p = tid; p < NPIX; p += blockDim.x) {
        int i = p / NN, j = p % NN;
        float val;
        if (ident) {
            val = src[p];
        } else {
            float xs = (float)j - 49.5f, ys = (float)i - 49.5f;
            float xq = ct * xs + st * ys + 49.5f;
            float yq = -st * xs + ct * ys + 49.5f;
            float x0f = floorf(xq), y0f = floorf(yq);
            float wx = xq - x0f, wy = yq - y0f;
            val = samp(src, y0f, x0f) * (1.f - wy) * (1.f - wx)
                + samp(src, y0f, x0f + 1.f) * (1.f - wy) * wx
                + samp(src, y0f + 1.f, x0f) * wy * (1.f - wx)
                + samp(src, y0f + 1.f, x0f + 1.f) * wy * wx;
        }
        rotT[j * 104 + i] = val;
    }
    __syncthreads();
    for (int task = tid; task < 5 * KXN; task += 256) {
        int kx = task % KXN;
        int y0 = (task / KXN) * 20;
        float sif, srf;
        sincosf(-3.14159265358979f * (float)kx * 0.01f, &sif, &srf);
        float wr = 1.f, wi = 0.f;
        float aR[20], aI[20];
#pragma unroll
        for (int i = 0; i < 20; i++) { aR[i] = 0.f; aI[i] = 0.f; }
        for (int x = 0; x < NN; x++) {
            if ((x & 24) && (x % 25 == 0)) {
                int j = (kx * (x / 25)) & 7;
                wr = C8[j]; wi = -S8[j];
            }
            const float4* rp = reinterpret_cast<const float4*>(&rotT[x * 104 + y0]);
#pragma unroll
            for (int q = 0; q < 5; q++) {
                float4 v = rp[q];
                aR[q*4+0] = fmaf(v.x, wr, aR[q*4+0]); aI[q*4+0] = fmaf(v.x, wi, aI[q*4+0]);
                aR[q*4+1] = fmaf(v.y, wr, aR[q*4+1]); aI[q*4+1] = fmaf(v.y, wi, aI[q*4+1]);
                aR[q*4+2] = fmaf(v.z, wr, aR[q*4+2]); aI[q*4+2] = fmaf(v.z, wi, aI[q*4+2]);
                aR[q*4+3] = fmaf(v.w, wr, aR[q*4+3]); aI[q*4+3] = fmaf(v.w, wi, aI[q*4+3]);
            }
            float nr = fmaf(wr, srf, -wi * sif);
            float ni = fmaf(wr, sif, wi * srf);
            wr = nr; wi = ni;
        }
#pragma unroll
        for (int i = 0; i < 20; i++)
            d_G[bid][y0 + i][kx] = make_float2(aR[i], aI[i]);
    }
}

// Complex accumulate with explicit twiddle (2 complex vals per float4)
#define CACC4(Tr, Ti, f4, twr, twi) \
    Tr[2*q]   = fmaf((f4).x, twr, Tr[2*q]);   Tr[2*q]   = fmaf(-(f4).y, twi, Tr[2*q]); \
    Ti[2*q]   = fmaf((f4).x, twi, Ti[2*q]);   Ti[2*q]   = fmaf( (f4).y, twr, Ti[2*q]); \
    Tr[2*q+1] = fmaf((f4).z, twr, Tr[2*q+1]); Tr[2*q+1] = fmaf(-(f4).w, twi, Tr[2*q+1]); \
    Ti[2*q+1] = fmaf((f4).z, twi, Ti[2*q+1]); Ti[2*q+1] = fmaf( (f4).w, twr, Ti[2*q+1]);

// Real accumulate Re(H * tw)
#define RACC4(E, f4, twr, twi) \
    E[2*q]   = fmaf((f4).x, twr, E[2*q]);   E[2*q]   = fmaf(-(f4).y, twi, E[2*q]); \
    E[2*q+1] = fmaf((f4).z, twr, E[2*q+1]); E[2*q+1] = fmaf(-(f4).w, twi, E[2*q+1]);

// ---------------- column DFT, RADIX-4, FACTORED twiddles --------------------
// Tc = w^c * Uc, Uc = sum_s G[4s+c] W^s, W = w^4, w = e^{-i pi u/100}.
// F[u+50j] = T0 + (-i)^j T1 + (-1)^j T2 + i^j T3.
__global__ void __launch_bounds__(256) k_coldft() {
    __shared__ __align__(16) float2 GT[NN][56];
    int img = blockIdx.x >> 1;
    int half = blockIdx.x & 1;
    int kxg0 = half * 52;
    int width = half ? 49 : 52;
    int tid = threadIdx.x;
    for (int t = tid; t < NN * 56; t += 256) {
        int y = t / 56, kxl = t % 56;
        GT[y][kxl] = (kxl < width) ? d_G[img][y][kxg0 + kxl] : make_float2(0.f, 0.f);
    }
    __syncthreads();
    for (int task = tid; task < 650; task += 256) {
        int u = task % 50;
        int kxl0 = (task / 50) * 4;
        float wbr, wbi;
        sincosf(-3.14159265358979f * (float)u * 0.01f, &wbi, &wbr);     // w
        float w2br = wbr * wbr - wbi * wbi,  w2bi = 2.f * wbr * wbi;    // w^2
        float w3br = w2br * wbr - w2bi * wbi, w3bi = w2br * wbi + w2bi * wbr; // w^3
        int uww = (u > 25) ? u - 50 : u;
        float Wr, Wi;
        sincosf(-6.28318530717959f * (float)uww * 0.02f, &Wi, &Wr);     // W = w^4
        float wsr = 1.f, wsi = 0.f;                                     // W^s
        float U0r[4], U0i[4], U1r[4], U1i[4], U2r[4], U2i[4], U3r[4], U3i[4];
#pragma unroll
        for (int j = 0; j < 4; j++) { U0r[j]=U0i[j]=U1r[j]=U1i[j]=U2r[j]=U2i[j]=U3r[j]=U3i[j]=0.f; }
        for (int s = 0; s < 25; s++) {
            const float4* p0 = reinterpret_cast<const float4*>(&GT[4*s    ][kxl0]);
            const float4* p1 = reinterpret_cast<const float4*>(&GT[4*s + 1][kxl0]);
            const float4* p2 = reinterpret_cast<const float4*>(&GT[4*s + 2][kxl0]);
            const float4* p3 = reinterpret_cast<const float4*>(&GT[4*s + 3][kxl0]);
#pragma unroll
            for (int q = 0; q < 2; q++) {
                float4 e0 = p0[q]; CACC4(U0r, U0i, e0, wsr, wsi)
                float4 e1 = p1[q]; CACC4(U1r, U1i, e1, wsr, wsi)
                float4 e2 = p2[q]; CACC4(U2r, U2i, e2, wsr, wsi)
                float4 e3 = p3[q]; CACC4(U3r, U3i, e3, wsr, wsi)
            }
            float nsr = wsr * Wr - wsi * Wi;
            float nsi = wsr * Wi + wsi * Wr;
            wsr = nsr; wsi = nsi;
        }
#pragma unroll
        for (int j = 0; j < 4; j++) {
            int kxl = kxl0 + j;
            if (kxl >= width) continue;
            int kx = kxg0 + kxl;
            float T0r = U0r[j],                       T0i = U0i[j];
            float T1r = wbr * U1r[j] - wbi * U1i[j],  T1i = wbr * U1i[j] + wbi * U1r[j];
            float T2r = w2br * U2r[j] - w2bi * U2i[j], T2i = w2br * U2i[j] + w2bi * U2r[j];
            float T3r = w3br * U3r[j] - w3bi * U3i[j], T3i = w3br * U3i[j] + w3bi * U3r[j];
            float acr = T0r + T2r, aci = T0i + T2i;
            float amr = T0r - T2r, ami = T0i - T2i;
            float bdr = T1r + T3r, bdi = T1i + T3i;
            float bmr = T1r - T3r, bmi = T1i - T3i;
            d_F[img][kx][u]       = make_float2(acr + bdr, aci + bdi);
            d_F[img][kx][u + 100] = make_float2(acr - bdr, aci - bdi);
            d_F[img][kx][u + 50]  = make_float2(amr + bmi, ami - bmr);   // j=1: am - i*bm
            d_F[img][kx][u + 150] = make_float2(amr - bmi, ami + bmr);   // j=3: am + i*bm
        }
    }
}

// ---------------- combine spectra + inverse ky (RADIX-4, factored) ----------
#define CACC(Sr, Si, f4) \
    Sr[2*q]   = fmaf((f4).x, wr, Sr[2*q]);   Sr[2*q]   = fmaf(-(f4).y, wi, Sr[2*q]); \
    Si[2*q]   = fmaf((f4).x, wi, Si[2*q]);   Si[2*q]   = fmaf( (f4).y, wr, Si[2*q]); \
    Sr[2*q+1] = fmaf((f4).z, wr, Sr[2*q+1]); Sr[2*q+1] = fmaf(-(f4).w, wi, Sr[2*q+1]); \
    Si[2*q+1] = fmaf((f4).z, wi, Si[2*q+1]); Si[2*q+1] = fmaf( (f4).w, wr, Si[2*q+1]);

__global__ void __launch_bounds__(320) k_combine_invy(const float* __restrict__ wb,
        const float* __restrict__ wc1, const float* __restrict__ wc2,
        const float* __restrict__ wk) {
    __shared__ __align__(16) float2 sfs[SS][24];
    __shared__ float2 ph[304];
    int chunk = blockIdx.x % 5;
    int imgH = blockIdx.x / 5;
    int b = imgH / RR;
    int r = imgH % RR;
    bool flip = (r >= RRH);
    int rb180 = flip ? r - RRH : r;
    int kxg0 = chunk * 24;
    int width = (KXN - kxg0 < 24) ? (KXN - kxg0) : 24;
    int tid = threadIdx.x;
    float w0 = *wb, w1v = *wc1, w2v = *wc2, w3 = *wk;
    int imgL0 = (b * RRH + rb180) * 2, imgL1 = imgL0 + 1;
    int imgR0 = NLIGH + b * 2, imgR1 = imgR0 + 1;
    if (flip) {
        for (int s = tid; s < 301; s += 320) {
            float pr, pi_;
            sincosf(3.14159265358979f * 0.01f * (float)s, &pi_, &pr);
            if (s & 1) { pr = -pr; pi_ = -pi_; }
            ph[s] = make_float2(pr, pi_);
        }
        __syncthreads();
    }
    for (int e = tid; e < SS * 24; e += 320) {
        int ky = e % SS, kxl = e / SS;
        float2 v = make_float2(0.f, 0.f);
        if (kxl < width) {
            int kx = kxg0 + kxl;
            float2 lb = d_F[imgL0][kx][ky];
            float2 lB = d_F[imgL1][kx][ky];
            if (flip) {
                float2 p = ph[kx + ky];
                float t;
                t    = p.x * lb.x + p.y * lb.y;
                lb.y = p.y * lb.x - p.x * lb.y;
                lb.x = t;
                t    = p.x * lB.x + p.y * lB.y;
                lB.y = p.y * lB.x - p.x * lB.y;
                lB.x = t;
            }
            float2 rb = d_F[imgR0][kx][ky];
            float2 rB = d_F[imgR1][kx][ky];
            float ur = w0 * lb.x + w1v * lB.x, ui = w0 * lb.y + w1v * lB.y;
            float vr = w2v * lb.x - w3 * lB.x, vi = w2v * lb.y - w3 * lB.y;
            v.x = rb.x * ur + rb.y * ui + rB.x * vr + rB.y * vi;
            v.y = rb.x * ui - rb.y * ur + rB.x * vi - rB.y * vr;
        }
        sfs[ky][kxl] = v;
    }
    __syncthreads();
    for (int task = tid; task < 300; task += 320) {
        int v = task % 50;
        int kxl0 = (task / 50) * 4;
        int vw = (v > 25) ? v - 50 : v;
        float sif, srf;
        sincosf(6.28318530717959f * (float)vw * 0.02f, &sif, &srf);
        float wr = 1.f, wi = 0.f;
        float S0r[4], S0i[4], S1r[4], S1i[4], S2r[4], S2i[4], S3r[4], S3i[4];
#pragma unroll
        for (int j = 0; j < 4; j++) { S0r[j]=S0i[j]=S1r[j]=S1i[j]=S2r[j]=S2i[j]=S3r[j]=S3i[j]=0.f; }
        for (int t = 0; t < 50; t++) {
            if (t == 25) {
                wr = (v & 1) ? -1.f : 1.f; wi = 0.f;
            }
            const float4* p0 = reinterpret_cast<const float4*>(&sfs[4*t    ][kxl0]);
            const float4* p1 = reinterpret_cast<const float4*>(&sfs[4*t + 1][kxl0]);
            const float4* p2 = reinterpret_cast<const float4*>(&sfs[4*t + 2][kxl0]);
            const float4* p3 = reinterpret_cast<const float4*>(&sfs[4*t + 3][kxl0]);
#pragma unroll
            for (int q = 0; q < 2; q++) {
                float4 e0 = p0[q]; CACC(S0r, S0i, e0)
                float4 e1 = p1[q]; CACC(S1r, S1i, e1)
                float4 e2 = p2[q]; CACC(S2r, S2i, e2)
                float4 e3 = p3[q]; CACC(S3r, S3i, e3)
            }
            float nr = fmaf(wr, srf, -wi * sif);
            float ni = fmaf(wr, sif, wi * srf);
            wr = nr; wi = ni;
        }
        float tr, ti;
        sincosf(3.14159265358979f * 0.01f * (float)v, &ti, &tr);
        float t2r = tr * tr - ti * ti, t2i = 2.f * tr * ti;
        float t3r = t2r * tr - t2i * ti, t3i = t2r * ti + t2i * tr;
#pragma unroll
        for (int j = 0; j < 4; j++) {
            int kxl = kxl0 + j;
            if (kxl >= width) continue;
            int kx = kxg0 + kxl;
            float ar = S0r[j], ai = S0i[j];
            float br = tr * S1r[j] - ti * S1i[j],   bi = tr * S1i[j] + ti * S1r[j];
            float cr = t2r * S2r[j] - t2i * S2i[j], ci = t2r * S2i[j] + t2i * S2r[j];
            float dr = t3r * S3r[j] - t3i * S3i[j], di = t3r * S3i[j] + t3i * S3r[j];
            float acr = ar + cr, aci = ai + ci;
            float amr = ar - cr, ami = ai - ci;
            float bdr = br + dr, bdi = bi + di;
            float bmr = br - dr, bmi = bi - di;
            d_H[imgH][kx][v]       = make_float2(acr + bdr, aci + bdi);
            d_H[imgH][kx][v + 100] = make_float2(acr - bdr, aci - bdi);
            d_H[imgH][kx][v + 50]  = make_float2(amr - bmi, ami + bmr);
            d_H[imgH][kx][v + 150] = make_float2(amr + bmi, ami - bmr);
        }
    }
}

// ---------------- inverse kx (real, RADIX-4, factored Z1/Z3) + reduce -------
// x = v+50j, w = e^{i pi v/100}.
// A0 = seed + sum_t 2Re(H[4t+4] w^{4t+4})  (real, stream*2)
// A2 = sum_t 2Re(H[4t+2] w^{4t+2})         (real, per-iter w^2)
// Z1 = sum_t H[4t+1] W^t ; Z3 = sum_t H[4t+3] W^t  (stream);  B1=w*Z1, B3=w^3*Z3
// s[v]=A0+A2+2(B1r+B3r); s[v+50]=A0-A2+2(B3i-B1i);
// s[v+100]=A0+A2-2(B1r+B3r); s[v+150]=A0-A2+2(B1i-B3i)
__global__ void __launch_bounds__(256) k_invx_reduce(const int* __restrict__ gtr,
                                                     const int* __restrict__ gtt) {
    __shared__ __align__(16) float2 HT[KXN][20];
    __shared__ float red[256];
    int yc = blockIdx.x % 10;
    int imgH = blockIdx.x / 10;
    int b = imgH / RR, r = imgH % RR;
    int ybase = yc * 20;
    int tid = threadIdx.x;
    for (int e = tid; e < KXN * 20; e += 256) {
        int kx = e / 20, yl = e % 20;
        HT[kx][yl] = d_H[imgH][kx][ybase + yl];
    }
    __syncthreads();
    int gr = gtr[b], t0 = gtt[2 * b], t1 = gtt[2 * b + 1];
    const float inv = 1.0f / 40000.0f;
    float lmax = -3.4e38f;
    for (int task = tid; task < 250; task += 256) {
        int v = task % 50;
        int y0 = (task / 50) * 4;
        float wbr, wbi;
        sincosf(3.14159265358979f * (float)v * 0.01f, &wbi, &wbr);      // w
        float w2br = wbr * wbr - wbi * wbi,  w2bi = 2.f * wbr * wbi;    // w^2
        float w3br = w2br * wbr - w2bi * wbi, w3bi = w2br * wbi + w2bi * wbr; // w^3
        int vw = (v > 25) ? v - 50 : v;
        float Wr, Wi;
        sincosf(6.28318530717959f * (float)vw * 0.02f, &Wi, &Wr);       // W = w^4
        float wsr = 1.f, wsi = 0.f;                                     // W^t
        float A0[4], A2[4], Z1r[4], Z1i[4], Z3r[4], Z3i[4];
        float sgn = (v & 1) ? -1.f : 1.f;
#pragma unroll
        for (int i = 0; i < 4; i++) {
            A0[i]  = HT[0][y0 + i].x + sgn * HT[100][y0 + i].x;
            A2[i]  = 0.f;
            Z1r[i] = 0.f; Z1i[i] = 0.f; Z3r[i] = 0.f; Z3i[i] = 0.f;
        }
        for (int t = 0; t < 25; t++) {
            float w2r = wsr * w2br - wsi * w2bi, w2i = wsr * w2bi + wsi * w2br; // w^{4t+2}
            float wnr = wsr * Wr - wsi * Wi,     wni = wsr * Wi + wsi * Wr;     // w^{4t+4}
            float e2r = 2.f * w2r, e2i = 2.f * w2i;
            float e0r = 2.f * wnr, e0i = 2.f * wni;
            const float4* p1 = reinterpret_cast<const float4*>(&HT[4*t + 1][y0]);
            const float4* p2 = reinterpret_cast<const float4*>(&HT[4*t + 2][y0]);
            const float4* p3 = reinterpret_cast<const float4*>(&HT[4*t + 3][y0]);
#pragma unroll
            for (int q = 0; q < 2; q++) {
                float4 h1 = p1[q]; CACC4(Z1r, Z1i, h1, wsr, wsi)
                float4 h2 = p2[q]; RACC4(A2, h2, e2r, e2i)
                float4 h3 = p3[q]; CACC4(Z3r, Z3i, h3, wsr, wsi)
            }
            if (t < 24) {
                const float4* p0 = reinterpret_cast<const float4*>(&HT[4*t + 4][y0]);
#pragma unroll
                for (int q = 0; q < 2; q++) {
                    float4 h0 = p0[q]; RACC4(A0, h0, e0r, e0i)
                }
            }
            wsr = wnr; wsi = wni;
        }
#pragma unroll
        for (int i = 0; i < 4; i++) {
            float b1r = wbr * Z1r[i] - wbi * Z1i[i],  b1i = wbr * Z1i[i] + wbi * Z1r[i];
            float b3r = w3br * Z3r[i] - w3bi * Z3i[i], b3i = w3br * Z3i[i] + w3bi * Z3r[i];
            float e0 = A0[i], e2 = A2[i];
            float cr = 2.f * (b1r + b3r);
            float di = 2.f * (b3i - b1i);
            float s0 = (e0 + e2 + cr) * inv;    // x = v
            float s1 = (e0 - e2 + di) * inv;    // x = v+50
            float s2 = (e0 + e2 - cr) * inv;    // x = v+100
            float s3 = (e0 - e2 - di) * inv;    // x = v+150
            lmax = fmaxf(lmax, fmaxf(fmaxf(s0, s1), fmaxf(s2, s3)));
            int y = ybase + y0 + i;
            if (r == gr && y == t0) {
                if (v == t1)       d_pos[b] = s0;
                if (v + 50 == t1)  d_pos[b] = s1;
                if (v + 100 == t1) d_pos[b] = s2;
                if (v + 150 == t1) d_pos[b] = s3;
            }
        }
    }
    red[tid] = lmax;
    __syncthreads();
    for (int s2 = 128; s2 > 0; s2 >>= 1) {
        if (tid < s2) red[tid] = fmaxf(red[tid], red[tid + s2]);
        __syncthreads();
    }
    if (tid == 0) atomicMax(&d_best[b], fenc(red[0]));
}

__global__ void k_final(float* __restrict__ out) {
    if (threadIdx.x == 0) {
        float lp = 0.f, ln = 0.f;
        for (int b = 0; b < NB; b++) {
            float p = d_pos[b];
            lp += p + p * p;
            float m = fdec(d_best[b]);
            ln += -m + m * m;
        }
        out[0] = lp / (float)NB;
        out[1] = ln / (float)NB;
    }
}

extern "C" void kernel_launch(void* const* d_in, const int* in_sizes, int n_in,
                              void* d_out, int out_size) {
    const float* rec = (const float*)d_in[0];
    const float* lig = (const float*)d_in[1];
    const float* w1 = (const float*)d_in[2];
    const float* w2 = (const float*)d_in[3];
    const float* wb = (const float*)d_in[4];
    const float* wc1 = (const float*)d_in[5];
    const float* wc2 = (const float*)d_in[6];
    const float* wk = (const float*)d_in[7];
    const int* gtr = (const int*)d_in[8];
    const int* gtt = (const int*)d_in[9];
    float* out = (float*)d_out;

    k_init<<<1, 32>>>();
    dim3 gconv((NPIX + 255) / 256, 4);
    k_conv1<<<gconv, 256>>>(rec, lig, w1);
    k_conv2<<<gconv, 256>>>(w2);
    k_rot_rowdft<<<NIMGH, 256>>>();
    k_coldft<<<NIMGH * 2, 256>>>();
    k_combine_invy<<<NB * RR * 5, 320>>>(wb, wc1, wc2, wk);
    k_invx_reduce<<<NB * RR * 10, 256>>>(gtr, gtt);
    k_final<<<1, 32>>>(out);
}

// round 14
// speedup vs baseline: 2.0145x; 1.2089x over previous
#include <cuda_runtime.h>
#include <math.h>

#define NB 2
#define RR 360
#define RRH 180
#define NN 100
#define SS 200
#define KXN 101
#define NPIX (NN*NN)
#define NLIGH (NB*RRH*2)
#define NIMGH (NLIGH + NB*2)
#define GPITCH 102
#define RT2 0.70710678118654752f

__device__ float  d_h1[4][9][NPIX];
__device__ float  d_feat[4][2][NPIX];
__device__ float2 d_G[NIMGH][NN][GPITCH];
__device__ float2 d_F[NIMGH][KXN][SS];
__device__ float2 d_H[NB*RR][KXN][SS];
__device__ unsigned int d_best[NB];
__device__ float  d_pos[NB];

__device__ __constant__ float C8[8] = {1.f, RT2, 0.f, -RT2, -1.f, -RT2, 0.f, RT2};
__device__ __constant__ float S8[8] = {0.f, RT2, 1.f, RT2, 0.f, -RT2, -1.f, -RT2};

__device__ __forceinline__ unsigned fenc(float f) {
    unsigned u = __float_as_uint(f);
    return (u & 0x80000000u) ? ~u : (u | 0x80000000u);
}
__device__ __forceinline__ float fdec(unsigned e) {
    unsigned u = (e & 0x80000000u) ? (e & 0x7FFFFFFFu) : ~e;
    return __uint_as_float(u);
}

__global__ void k_init() {
    int t = threadIdx.x;
    if (t < NB) { d_best[t] = 0u; d_pos[t] = 0.0f; }
}

// ---------------- conv1 + norm_relu (FIELDS1) -------------------------------
__global__ void k_conv1(const float* __restrict__ rec, const float* __restrict__ lig,
                        const float* __restrict__ w1) {
    int img = blockIdx.y;
    int p = blockIdx.x * blockDim.x + threadIdx.x;
    if (p >= NPIX) return;
    int y = p / NN, x = p % NN;
    const float* src = (img < NB) ? (rec + img * NPIX) : (lig + (img - NB) * NPIX);
    float acc[9];
#pragma unroll
    for (int o = 0; o < 9; o++) acc[o] = 0.0f;
#pragma unroll
    for (int ky = 0; ky < 5; ky++) {
        int iy = y + ky - 2;
        if ((unsigned)iy >= NN) continue;
#pragma unroll
        for (int kx = 0; kx < 5; kx++) {
            int ix = x + kx - 2;
            if ((unsigned)ix >= NN) continue;
            float v = __ldg(src + iy * NN + ix);
#pragma unroll
            for (int o = 0; o < 9; o++)
                acc[o] = fmaf(v, __ldg(w1 + o * 25 + ky * 5 + kx), acc[o]);
        }
    }
    {
        float a = acc[0];
        float n = sqrtf(a * a + 1e-12f);
        d_h1[img][0][p] = a * (n / (n + 1e-12f));
    }
#pragma unroll
    for (int g = 0; g < 4; g++) {
        int s = 1 + 2 * g;
        float a = acc[s], b = acc[s + 1];
        float n = sqrtf(a * a + b * b + 1e-12f);
        float sc = n / (n + 1e-12f);
        d_h1[img][s][p] = a * sc;
        d_h1[img][s + 1][p] = b * sc;
    }
}

// ---------------- conv2 + norm_relu (FIELDS2) + features --------------------
__global__ void k_conv2(const float* __restrict__ w2) {
    int img = blockIdx.y;
    int p = blockIdx.x * blockDim.x + threadIdx.x;
    if (p >= NPIX) return;
    int y = p / NN, x = p % NN;
    float acc[3] = {0.f, 0.f, 0.f};
    for (int ci = 0; ci < 9; ci++) {
        const float* hp = d_h1[img][ci];
#pragma unroll
        for (int ky = 0; ky < 5; ky++) {
            int iy = y + ky - 2;
            if ((unsigned)iy >= NN) continue;
#pragma unroll
            for (int kx = 0; kx < 5; kx++) {
                int ix = x + kx - 2;
                if ((unsigned)ix >= NN) continue;
                float v = hp[iy * NN + ix];
#pragma unroll
                for (int o = 0; o < 3; o++)
                    acc[o] = fmaf(v, __ldg(w2 + ((o * 9 + ci) * 5 + ky) * 5 + kx), acc[o]);
            }
        }
    }
    float o0, o1, o2;
    {
        float a = acc[0];
        float n = sqrtf(a * a + 1e-12f);
        o0 = a * (n / (n + 1e-12f));
    }
    {
        float a = acc[1], b = acc[2];
        float n = sqrtf(a * a + b * b + 1e-12f);
        float sc = n / (n + 1e-12f);
        o1 = a * sc; o2 = b * sc;
    }
    d_feat[img][0][p] = fabsf(o0);
    d_feat[img][1][p] = sqrtf(o1 * o1 + o2 * o2 + 1e-12f);
}

__device__ __forceinline__ float samp(const float* __restrict__ im, float yf, float xf) {
    if (yf < 0.f || yf >= 100.f || xf < 0.f || xf >= 100.f) return 0.f;
    int yc = (int)yf, xc = (int)xf;
    return im[yc * NN + xc];
}

// ---------------- rotate (fused) + row DFT ----------------------------------
__global__ void __launch_bounds__(256) k_rot_rowdft() {
    __shared__ __align__(16) float rotT[NN * 104];
    int bid = blockIdx.x;
    int tid = threadIdx.x;
    const float* src;
    bool ident;
    float ct = 1.f, st = 0.f;
    if (bid < NLIGH) {
        int c = bid & 1;
        int r = (bid >> 1) % RRH;
        int b = bid / (2 * RRH);
        src = d_feat[NB + b][c];
        double th = -3.14159265358979323846 + (double)r * (6.283185307179586477 / 360.0);
        ct = (float)cos(th); st = (float)sin(th);
        ident = false;
    } else {
        int i = bid - NLIGH;
        src = d_feat[i >> 1][i & 1];
        ident = true;
    }
    for (int p = tid; p < NPIX; p += blockDim.x) {
        int i = p / NN, j = p % NN;
        float val;
        if (ident) {
            val = src[p];
        } else {
            float xs = (float)j - 49.5f, ys = (float)i - 49.5f;
            float xq = ct * xs + st * ys + 49.5f;
            float yq = -st * xs + ct * ys + 49.5f;
            float x0f = floorf(xq), y0f = floorf(yq);
            float wx = xq - x0f, wy = yq - y0f;
            val = samp(src, y0f, x0f) * (1.f - wy) * (1.f - wx)
                + samp(src, y0f, x0f + 1.f) * (1.f - wy) * wx
                + samp(src, y0f + 1.f, x0f) * wy * (1.f - wx)
                + samp(src, y0f + 1.f, x0f + 1.f) * wy * wx;
        }
        rotT[j * 104 + i] = val;
    }
    __syncthreads();
    for (int task = tid; task < 5 * KXN; task += 256) {
        int kx = task % KXN;
        int y0 = (task / KXN) * 20;
        float sif, srf;
        sincosf(-3.14159265358979f * (float)kx * 0.01f, &sif, &srf);
        float wr = 1.f, wi = 0.f;
        float aR[20], aI[20];
#pragma unroll
        for (int i = 0; i < 20; i++) { aR[i] = 0.f; aI[i] = 0.f; }
        for (int x = 0; x < NN; x++) {
            if ((x & 24) && (x % 25 == 0)) {
                int j = (kx * (x / 25)) & 7;
                wr = C8[j]; wi = -S8[j];
            }
            const float4* rp = reinterpret_cast<const float4*>(&rotT[x * 104 + y0]);
#pragma unroll
            for (int q = 0; q < 5; q++) {
                float4 v = rp[q];
                aR[q*4+0] = fmaf(v.x, wr, aR[q*4+0]); aI[q*4+0] = fmaf(v.x, wi, aI[q*4+0]);
                aR[q*4+1] = fmaf(v.y, wr, aR[q*4+1]); aI[q*4+1] = fmaf(v.y, wi, aI[q*4+1]);
                aR[q*4+2] = fmaf(v.z, wr, aR[q*4+2]); aI[q*4+2] = fmaf(v.z, wi, aI[q*4+2]);
                aR[q*4+3] = fmaf(v.w, wr, aR[q*4+3]); aI[q*4+3] = fmaf(v.w, wi, aI[q*4+3]);
            }
            float nr = fmaf(wr, srf, -wi * sif);
            float ni = fmaf(wr, sif, wi * srf);
            wr = nr; wi = ni;
        }
#pragma unroll
        for (int i = 0; i < 20; i++)
            d_G[bid][y0 + i][kx] = make_float2(aR[i], aI[i]);
    }
}

// Complex accumulate with explicit twiddle (2 complex vals per float4)
#define CACC4(Tr, Ti, f4, twr, twi) \
    Tr[2*q]   = fmaf((f4).x, twr, Tr[2*q]);   Tr[2*q]   = fmaf(-(f4).y, twi, Tr[2*q]); \
    Ti[2*q]   = fmaf((f4).x, twi, Ti[2*q]);   Ti[2*q]   = fmaf( (f4).y, twr, Ti[2*q]); \
    Tr[2*q+1] = fmaf((f4).z, twr, Tr[2*q+1]); Tr[2*q+1] = fmaf(-(f4).w, twi, Tr[2*q+1]); \
    Ti[2*q+1] = fmaf((f4).z, twi, Ti[2*q+1]); Ti[2*q+1] = fmaf( (f4).w, twr, Ti[2*q+1]);

// ---------------- column DFT, RADIX-4, FACTORED twiddles --------------------
// Tc = w^c * Uc, Uc = sum_s G[4s+c] W^s, W = w^4, w = e^{-i pi u/100}.
// F[u+50j] = T0 + (-i)^j T1 + (-1)^j T2 + i^j T3.
__global__ void __launch_bounds__(256) k_coldft() {
    __shared__ __align__(16) float2 GT[NN][56];
    int img = blockIdx.x >> 1;
    int half = blockIdx.x & 1;
    int kxg0 = half * 52;
    int width = half ? 49 : 52;
    int tid = threadIdx.x;
    for (int t = tid; t < NN * 56; t += 256) {
        int y = t / 56, kxl = t % 56;
        GT[y][kxl] = (kxl < width) ? d_G[img][y][kxg0 + kxl] : make_float2(0.f, 0.f);
    }
    __syncthreads();
    for (int task = tid; task < 650; task += 256) {
        int u = task % 50;
        int kxl0 = (task / 50) * 4;
        float wbr, wbi;
        sincosf(-3.14159265358979f * (float)u * 0.01f, &wbi, &wbr);
        float w2br = wbr * wbr - wbi * wbi,  w2bi = 2.f * wbr * wbi;
        float w3br = w2br * wbr - w2bi * wbi, w3bi = w2br * wbi + w2bi * wbr;
        int uww = (u > 25) ? u - 50 : u;
        float Wr, Wi;
        sincosf(-6.28318530717959f * (float)uww * 0.02f, &Wi, &Wr);
        float wsr = 1.f, wsi = 0.f;
        float U0r[4], U0i[4], U1r[4], U1i[4], U2r[4], U2i[4], U3r[4], U3i[4];
#pragma unroll
        for (int j = 0; j < 4; j++) { U0r[j]=U0i[j]=U1r[j]=U1i[j]=U2r[j]=U2i[j]=U3r[j]=U3i[j]=0.f; }
        for (int s = 0; s < 25; s++) {
            const float4* p0 = reinterpret_cast<const float4*>(&GT[4*s    ][kxl0]);
            const float4* p1 = reinterpret_cast<const float4*>(&GT[4*s + 1][kxl0]);
            const float4* p2 = reinterpret_cast<const float4*>(&GT[4*s + 2][kxl0]);
            const float4* p3 = reinterpret_cast<const float4*>(&GT[4*s + 3][kxl0]);
#pragma unroll
            for (int q = 0; q < 2; q++) {
                float4 e0 = p0[q]; CACC4(U0r, U0i, e0, wsr, wsi)
                float4 e1 = p1[q]; CACC4(U1r, U1i, e1, wsr, wsi)
                float4 e2 = p2[q]; CACC4(U2r, U2i, e2, wsr, wsi)
                float4 e3 = p3[q]; CACC4(U3r, U3i, e3, wsr, wsi)
            }
            float nsr = wsr * Wr - wsi * Wi;
            float nsi = wsr * Wi + wsi * Wr;
            wsr = nsr; wsi = nsi;
        }
#pragma unroll
        for (int j = 0; j < 4; j++) {
            int kxl = kxl0 + j;
            if (kxl >= width) continue;
            int kx = kxg0 + kxl;
            float T0r = U0r[j],                       T0i = U0i[j];
            float T1r = wbr * U1r[j] - wbi * U1i[j],  T1i = wbr * U1i[j] + wbi * U1r[j];
            float T2r = w2br * U2r[j] - w2bi * U2i[j], T2i = w2br * U2i[j] + w2bi * U2r[j];
            float T3r = w3br * U3r[j] - w3bi * U3i[j], T3i = w3br * U3i[j] + w3bi * U3r[j];
            float acr = T0r + T2r, aci = T0i + T2i;
            float amr = T0r - T2r, ami = T0i - T2i;
            float bdr = T1r + T3r, bdi = T1i + T3i;
            float bmr = T1r - T3r, bmi = T1i - T3i;
            d_F[img][kx][u]       = make_float2(acr + bdr, aci + bdi);
            d_F[img][kx][u + 100] = make_float2(acr - bdr, aci - bdi);
            d_F[img][kx][u + 50]  = make_float2(amr + bmi, ami - bmr);
            d_F[img][kx][u + 150] = make_float2(amr - bmi, ami + bmr);
        }
    }
}

// ---------------- combine spectra + inverse ky (RADIX-8) --------------------
// ky = 8t+c, y = v+25j. S_c = sum_t sf[8t+c] W^t, W = e^{2pi i v/25}.
// T_c = w^c S_c, w = e^{i pi v/100}.  H[v+25j] = sum_c T_c e^{i pi c j/4}.
// Butterfly: even c -> E_j (4pt), odd c -> G_j (4pt), O_j = e^{i pi j/4} G_j;
// H_j = E_j + O_j, H_{j+4} = E_j - O_j.
__global__ void __launch_bounds__(320) k_combine_invy(const float* __restrict__ wb,
        const float* __restrict__ wc1, const float* __restrict__ wc2,
        const float* __restrict__ wk) {
    __shared__ __align__(16) float2 sfs[SS][24];
    __shared__ float2 ph[304];
    int chunk = blockIdx.x % 5;
    int imgH = blockIdx.x / 5;
    int b = imgH / RR;
    int r = imgH % RR;
    bool flip = (r >= RRH);
    int rb180 = flip ? r - RRH : r;
    int kxg0 = chunk * 24;
    int width = (KXN - kxg0 < 24) ? (KXN - kxg0) : 24;
    int tid = threadIdx.x;
    float w0 = *wb, w1v = *wc1, w2v = *wc2, w3v = *wk;
    int imgL0 = (b * RRH + rb180) * 2, imgL1 = imgL0 + 1;
    int imgR0 = NLIGH + b * 2, imgR1 = imgR0 + 1;
    if (flip) {
        for (int s = tid; s < 301; s += 320) {
            float pr, pi_;
            sincosf(3.14159265358979f * 0.01f * (float)s, &pi_, &pr);
            if (s & 1) { pr = -pr; pi_ = -pi_; }
            ph[s] = make_float2(pr, pi_);
        }
        __syncthreads();
    }
    for (int e = tid; e < SS * 24; e += 320) {
        int ky = e % SS, kxl = e / SS;
        float2 v = make_float2(0.f, 0.f);
        if (kxl < width) {
            int kx = kxg0 + kxl;
            float2 lb = d_F[imgL0][kx][ky];
            float2 lB = d_F[imgL1][kx][ky];
            if (flip) {
                float2 p = ph[kx + ky];
                float t;
                t    = p.x * lb.x + p.y * lb.y;
                lb.y = p.y * lb.x - p.x * lb.y;
                lb.x = t;
                t    = p.x * lB.x + p.y * lB.y;
                lB.y = p.y * lB.x - p.x * lB.y;
                lB.x = t;
            }
            float2 rb = d_F[imgR0][kx][ky];
            float2 rB = d_F[imgR1][kx][ky];
            float ur = w0 * lb.x + w1v * lB.x, ui = w0 * lb.y + w1v * lB.y;
            float vr = w2v * lb.x - w3v * lB.x, vi = w2v * lb.y - w3v * lB.y;
            v.x = rb.x * ur + rb.y * ui + rB.x * vr + rB.y * vi;
            v.y = rb.x * ui - rb.y * ur + rB.x * vi - rB.y * vr;
        }
        sfs[ky][kxl] = v;
    }
    __syncthreads();
    // 300 tasks = 12 kx-groups of 2 x 25 v (v fastest)
    for (int task = tid; task < 300; task += 320) {
        int v = task % 25;
        int kxl0 = (task / 25) * 2;
        int vw = (v > 12) ? v - 25 : v;
        float Wi_, Wr_;
        sincosf(6.28318530717959f * (float)vw * 0.04f, &Wi_, &Wr_);   // W = e^{2pi i v/25}
        float wsr = 1.f, wsi = 0.f;
        float S0r[2], S0i[2], S1r[2], S1i[2], S2r[2], S2i[2], S3r[2], S3i[2];
        float S4r[2], S4i[2], S5r[2], S5i[2], S6r[2], S6i[2], S7r[2], S7i[2];
#pragma unroll
        for (int j = 0; j < 2; j++) {
            S0r[j]=S0i[j]=S1r[j]=S1i[j]=S2r[j]=S2i[j]=S3r[j]=S3i[j]=0.f;
            S4r[j]=S4i[j]=S5r[j]=S5i[j]=S6r[j]=S6i[j]=S7r[j]=S7i[j]=0.f;
        }
        for (int t = 0; t < 25; t++) {
            const int q = 0;
            float4 e0 = *reinterpret_cast<const float4*>(&sfs[8*t    ][kxl0]); CACC4(S0r, S0i, e0, wsr, wsi)
            float4 e1 = *reinterpret_cast<const float4*>(&sfs[8*t + 1][kxl0]); CACC4(S1r, S1i, e1, wsr, wsi)
            float4 e2 = *reinterpret_cast<const float4*>(&sfs[8*t + 2][kxl0]); CACC4(S2r, S2i, e2, wsr, wsi)
            float4 e3 = *reinterpret_cast<const float4*>(&sfs[8*t + 3][kxl0]); CACC4(S3r, S3i, e3, wsr, wsi)
            float4 e4 = *reinterpret_cast<const float4*>(&sfs[8*t + 4][kxl0]); CACC4(S4r, S4i, e4, wsr, wsi)
            float4 e5 = *reinterpret_cast<const float4*>(&sfs[8*t + 5][kxl0]); CACC4(S5r, S5i, e5, wsr, wsi)
            float4 e6 = *reinterpret_cast<const float4*>(&sfs[8*t + 6][kxl0]); CACC4(S6r, S6i, e6, wsr, wsi)
            float4 e7 = *reinterpret_cast<const float4*>(&sfs[8*t + 7][kxl0]); CACC4(S7r, S7i, e7, wsr, wsi)
            float nsr = wsr * Wr_ - wsi * Wi_;
            float nsi = wsr * Wi_ + wsi * Wr_;
            wsr = nsr; wsi = nsi;
        }
        // w powers
        float w1r_, w1i_, w2r_, w2i_;
        sincosf(3.14159265358979f * (float)v * 0.01f, &w1i_, &w1r_);   // w
        sincosf(3.14159265358979f * (float)v * 0.02f, &w2i_, &w2r_);   // w^2
        float w3r_ = w1r_*w2r_ - w1i_*w2i_, w3i_ = w1r_*w2i_ + w1i_*w2r_;
        float w4r_ = w2r_*w2r_ - w2i_*w2i_, w4i_ = 2.f*w2r_*w2i_;
        float w5r_ = w2r_*w3r_ - w2i_*w3i_, w5i_ = w2r_*w3i_ + w2i_*w3r_;
        float w6r_ = w3r_*w3r_ - w3i_*w3i_, w6i_ = 2.f*w3r_*w3i_;
        float w7r_ = w3r_*w4r_ - w3i_*w4i_, w7i_ = w3r_*w4i_ + w3i_*w4r_;
#pragma unroll
        for (int jj = 0; jj < 2; jj++) {
            int kxl = kxl0 + jj;
            if (kxl >= width) continue;
            int kx = kxg0 + kxl;
            float V1r = w1r_*S1r[jj] - w1i_*S1i[jj], V1i = w1r_*S1i[jj] + w1i_*S1r[jj];
            float V2r = w2r_*S2r[jj] - w2i_*S2i[jj], V2i = w2r_*S2i[jj] + w2i_*S2r[jj];
            float V3r = w3r_*S3r[jj] - w3i_*S3i[jj], V3i = w3r_*S3i[jj] + w3i_*S3r[jj];
            float V4r = w4r_*S4r[jj] - w4i_*S4i[jj], V4i = w4r_*S4i[jj] + w4i_*S4r[jj];
            float V5r = w5r_*S5r[jj] - w5i_*S5i[jj], V5i = w5r_*S5i[jj] + w5i_*S5r[jj];
            float V6r = w6r_*S6r[jj] - w6i_*S6i[jj], V6i = w6r_*S6i[jj] + w6i_*S6r[jj];
            float V7r = w7r_*S7r[jj] - w7i_*S7i[jj], V7i = w7r_*S7i[jj] + w7i_*S7r[jj];
            float acr = S0r[jj] + V4r, aci = S0i[jj] + V4i;
            float amr = S0r[jj] - V4r, ami = S0i[jj] - V4i;
            float bdr = V2r + V6r, bdi = V2i + V6i;
            float bmr = V2r - V6r, bmi = V2i - V6i;
            float E0r = acr + bdr, E0i = aci + bdi;
            float E2r = acr - bdr, E2i = aci - bdi;
            float E1r = amr - bmi, E1i = ami + bmr;
            float E3r = amr + bmi, E3i = ami - bmr;
            float pcr = V1r + V5r, pci = V1i + V5i;
            float pmr = V1r - V5r, pmi = V1i - V5i;
            float qdr = V3r + V7r, qdi = V3i + V7i;
            float qmr = V3r - V7r, qmi = V3i - V7i;
            float G0r = pcr + qdr, G0i = pci + qdi;
            float G2r = pcr - qdr, G2i = pci - qdi;
            float G1r = pmr - qmi, G1i = pmi + qmr;
            float G3r = pmr + qmi, G3i = pmi - qmr;
            float O0r = G0r,               O0i = G0i;
            float O1r = RT2 * (G1r - G1i), O1i = RT2 * (G1r + G1i);
            float O2r = -G2i,              O2i = G2r;
            float O3r = -RT2 * (G3r + G3i), O3i = RT2 * (G3r - G3i);
            d_H[imgH][kx][v]       = make_float2(E0r + O0r, E0i + O0i);
            d_H[imgH][kx][v + 100] = make_float2(E0r - O0r, E0i - O0i);
            d_H[imgH][kx][v + 25]  = make_float2(E1r + O1r, E1i + O1i);
            d_H[imgH][kx][v + 125] = make_float2(E1r - O1r, E1i - O1i);
            d_H[imgH][kx][v + 50]  = make_float2(E2r + O2r, E2i + O2i);
            d_H[imgH][kx][v + 150] = make_float2(E2r - O2r, E2i - O2i);
            d_H[imgH][kx][v + 75]  = make_float2(E3r + O3r, E3i + O3i);
            d_H[imgH][kx][v + 175] = make_float2(E3r - O3r, E3i - O3i);
        }
    }
}

// ---------------- inverse kx (real, RADIX-8) + reduce -----------------------
// s[x] = sum_{kx classes} 2Re(w^c Z_c e^{i pi c j/4}), x = v+25j,
// Z_c = sum_{t=0..12} H'[8t+c] W^t;  H' has rows 0 and 100 pre-halved,
// rows 101..103 zero (uniform loop, no DC/Nyquist special cases).
__global__ void __launch_bounds__(256) k_invx_reduce(const int* __restrict__ gtr,
                                                     const int* __restrict__ gtt) {
    __shared__ __align__(16) float2 HT[104][20];
    __shared__ float red[256];
    int yc = blockIdx.x % 10;
    int imgH = blockIdx.x / 10;
    int b = imgH / RR, r = imgH % RR;
    int ybase = yc * 20;
    int tid = threadIdx.x;
    for (int e = tid; e < 104 * 20; e += 256) {
        int kx = e / 20, yl = e % 20;
        float2 val = make_float2(0.f, 0.f);
        if (kx < KXN) {
            val = d_H[imgH][kx][ybase + yl];
            if (kx == 0 || kx == 100) { val.x *= 0.5f; val.y *= 0.5f; }
        }
        HT[kx][yl] = val;
    }
    __syncthreads();
    int gr = gtr[b], t0 = gtt[2 * b], t1 = gtt[2 * b + 1];
    const float inv = 1.0f / 40000.0f;
    float lmax = -3.4e38f;
    // 250 tasks = 10 y-groups of 2 x 25 v (v fastest)
    for (int task = tid; task < 250; task += 256) {
        int v = task % 25;
        int y0 = (task / 25) * 2;
        int vw = (v > 12) ? v - 25 : v;
        float Wi_, Wr_;
        sincosf(6.28318530717959f * (float)vw * 0.04f, &Wi_, &Wr_);   // W = e^{2pi i v/25}
        float wsr = 1.f, wsi = 0.f;
        float Z0r[2], Z0i[2], Z1r[2], Z1i[2], Z2r[2], Z2i[2], Z3r[2], Z3i[2];
        float Z4r[2], Z4i[2], Z5r[2], Z5i[2], Z6r[2], Z6i[2], Z7r[2], Z7i[2];
#pragma unroll
        for (int j = 0; j < 2; j++) {
            Z0r[j]=Z0i[j]=Z1r[j]=Z1i[j]=Z2r[j]=Z2i[j]=Z3r[j]=Z3i[j]=0.f;
            Z4r[j]=Z4i[j]=Z5r[j]=Z5i[j]=Z6r[j]=Z6i[j]=Z7r[j]=Z7i[j]=0.f;
        }
        for (int t = 0; t < 13; t++) {
            const int q = 0;
            float4 h0 = *reinterpret_cast<const float4*>(&HT[8*t    ][y0]); CACC4(Z0r, Z0i, h0, wsr, wsi)
            float4 h1 = *reinterpret_cast<const float4*>(&HT[8*t + 1][y0]); CACC4(Z1r, Z1i, h1, wsr, wsi)
            float4 h2 = *reinterpret_cast<const float4*>(&HT[8*t + 2][y0]); CACC4(Z2r, Z2i, h2, wsr, wsi)
            float4 h3 = *reinterpret_cast<const float4*>(&HT[8*t + 3][y0]); CACC4(Z3r, Z3i, h3, wsr, wsi)
            float4 h4 = *reinterpret_cast<const float4*>(&HT[8*t + 4][y0]); CACC4(Z4r, Z4i, h4, wsr, wsi)
            float4 h5 = *reinterpret_cast<const float4*>(&HT[8*t + 5][y0]); CACC4(Z5r, Z5i, h5, wsr, wsi)
            float4 h6 = *reinterpret_cast<const float4*>(&HT[8*t + 6][y0]); CACC4(Z6r, Z6i, h6, wsr, wsi)
            float4 h7 = *reinterpret_cast<const float4*>(&HT[8*t + 7][y0]); CACC4(Z7r, Z7i, h7, wsr, wsi)
            float nsr = wsr * Wr_ - wsi * Wi_;
            float nsi = wsr * Wi_ + wsi * Wr_;
            wsr = nsr; wsi = nsi;
        }
        float w1r_, w1i_, w2r_, w2i_;
        sincosf(3.14159265358979f * (float)v * 0.01f, &w1i_, &w1r_);
        sincosf(3.14159265358979f * (float)v * 0.02f, &w2i_, &w2r_);
        float w3r_ = w1r_*w2r_ - w1i_*w2i_, w3i_ = w1r_*w2i_ + w1i_*w2r_;
        float w4r_ = w2r_*w2r_ - w2i_*w2i_, w4i_ = 2.f*w2r_*w2i_;
        float w5r_ = w2r_*w3r_ - w2i_*w3i_, w5i_ = w2r_*w3i_ + w2i_*w3r_;
        float w6r_ = w3r_*w3r_ - w3i_*w3i_, w6i_ = 2.f*w3r_*w3i_;
        float w7r_ = w3r_*w4r_ - w3i_*w4i_, w7i_ = w3r_*w4i_ + w3i_*w4r_;
#pragma unroll
        for (int i = 0; i < 2; i++) {
            float V1r = w1r_*Z1r[i] - w1i_*Z1i[i], V1i = w1r_*Z1i[i] + w1i_*Z1r[i];
            float V2r = w2r_*Z2r[i] - w2i_*Z2i[i], V2i = w2r_*Z2i[i] + w2i_*Z2r[i];
            float V3r = w3r_*Z3r[i] - w3i_*Z3i[i], V3i = w3r_*Z3i[i] + w3i_*Z3r[i];
            float V4r = w4r_*Z4r[i] - w4i_*Z4i[i], V4i = w4r_*Z4i[i] + w4i_*Z4r[i];
            float V5r = w5r_*Z5r[i] - w5i_*Z5i[i], V5i = w5r_*Z5i[i] + w5i_*Z5r[i];
            float V6r = w6r_*Z6r[i] - w6i_*Z6i[i], V6i = w6r_*Z6i[i] + w6i_*Z6r[i];
            float V7r = w7r_*Z7r[i] - w7i_*Z7i[i], V7i = w7r_*Z7i[i] + w7i_*Z7r[i];
            float acr = Z0r[i] + V4r, aci = Z0i[i] + V4i;
            float amr = Z0r[i] - V4r, ami = Z0i[i] - V4i;
            float bdr = V2r + V6r, bdi = V2i + V6i;
            float bmr = V2r - V6r, bmi = V2i - V6i;
            float E0r = acr + bdr;
            float E2r = acr - bdr;
            float E1r = amr - bmi;
            float E3r = amr + bmi;
            float pcr = V1r + V5r, pci = V1i + V5i;
            float pmr = V1r - V5r, pmi = V1i - V5i;
            float qdr = V3r + V7r, qdi = V3i + V7i;
            float qmr = V3r - V7r, qmi = V3i - V7i;
            float G0r = pcr + qdr;
            float G2i = pci - qdi;
            float G1r = pmr - qmi, G1i = pmi + qmr;
            float G3r = pmr + qmi, G3i = pmi - qmr;
            float O0r = G0r;
            float O1r = RT2 * (G1r - G1i);
            float O2r = -G2i;
            float O3r = -RT2 * (G3r + G3i);
            float sc = 2.f * inv;
            float s[8];
            s[0] = (E0r + O0r) * sc;  s[4] = (E0r - O0r) * sc;
            s[1] = (E1r + O1r) * sc;  s[5] = (E1r - O1r) * sc;
            s[2] = (E2r + O2r) * sc;  s[6] = (E2r - O2r) * sc;
            s[3] = (E3r + O3r) * sc;  s[7] = (E3r - O3r) * sc;
#pragma unroll
            for (int j = 0; j < 8; j++) lmax = fmaxf(lmax, s[j]);
            int y = ybase + y0 + i;
            if (r == gr && y == t0) {
#pragma unroll
                for (int j = 0; j < 8; j++)
                    if (v + 25 * j == t1) d_pos[b] = s[j];
            }
        }
    }
    red[tid] = lmax;
    __syncthreads();
    for (int s2 = 128; s2 > 0; s2 >>= 1) {
        if (tid < s2) red[tid] = fmaxf(red[tid], red[tid + s2]);
        __syncthreads();
    }
    if (tid == 0) atomicMax(&d_best[b], fenc(red[0]));
}

__global__ void k_final(float* __restrict__ out) {
    if (threadIdx.x == 0) {
        float lp = 0.f, ln = 0.f;
        for (int b = 0; b < NB; b++) {
            float p = d_pos[b];
            lp += p + p * p;
            float m = fdec(d_best[b]);
            ln += -m + m * m;
        }
        out[0] = lp / (float)NB;
        out[1] = ln / (float)NB;
    }
}

extern "C" void kernel_launch(void* const* d_in, const int* in_sizes, int n_in,
                              void* d_out, int out_size) {
    const float* rec = (const float*)d_in[0];
    const float* lig = (const float*)d_in[1];
    const float* w1 = (const float*)d_in[2];
    const float* w2 = (const float*)d_in[3];
    const float* wb = (const float*)d_in[4];
    const float* wc1 = (const float*)d_in[5];
    const float* wc2 = (const float*)d_in[6];
    const float* wk = (const float*)d_in[7];
    const int* gtr = (const int*)d_in[8];
    const int* gtt = (const int*)d_in[9];
    float* out = (float*)d_out;

    k_init<<<1, 32>>>();
    dim3 gconv((NPIX + 255) / 256, 4);
    k_conv1<<<gconv, 256>>>(rec, lig, w1);
    k_conv2<<<gconv, 256>>>(w2);
    k_rot_rowdft<<<NIMGH, 256>>>();
    k_coldft<<<NIMGH * 2, 256>>>();
    k_combine_invy<<<NB * RR * 5, 320>>>(wb, wc1, wc2, wk);
    k_invx_reduce<<<NB * RR * 10, 256>>>(gtr, gtt);
    k_final<<<1, 32>>>(out);
}

// round 15
// speedup vs baseline: 2.1469x; 1.0657x over previous
#include <cuda_runtime.h>
#include <math.h>

#define NB 2
#define RR 360
#define RRH 180
#define NN 100
#define SS 200
#define KXN 101
#define NPIX (NN*NN)
#define NLIGH (NB*RRH*2)
#define NIMGH (NLIGH + NB*2)
#define GPITCH 102
#define RT2 0.70710678118654752f

__device__ float  d_h1[4][9][NPIX];
__device__ float  d_feat[4][2][NPIX];
__device__ float2 d_G[NIMGH][NN][GPITCH];
__device__ float2 d_F[NIMGH][KXN][SS];
__device__ float2 d_H[NB*RR][KXN][SS];
__device__ unsigned int d_best[NB];
__device__ float  d_pos[NB];

__device__ __forceinline__ unsigned fenc(float f) {
    unsigned u = __float_as_uint(f);
    return (u & 0x80000000u) ? ~u : (u | 0x80000000u);
}
__device__ __forceinline__ float fdec(unsigned e) {
    unsigned u = (e & 0x80000000u) ? (e & 0x7FFFFFFFu) : ~e;
    return __uint_as_float(u);
}

__global__ void k_init() {
    int t = threadIdx.x;
    if (t < NB) { d_best[t] = 0u; d_pos[t] = 0.0f; }
}

// ---------------- conv1 + norm_relu (FIELDS1) -------------------------------
__global__ void k_conv1(const float* __restrict__ rec, const float* __restrict__ lig,
                        const float* __restrict__ w1) {
    int img = blockIdx.y;
    int p = blockIdx.x * blockDim.x + threadIdx.x;
    if (p >= NPIX) return;
    int y = p / NN, x = p % NN;
    const float* src = (img < NB) ? (rec + img * NPIX) : (lig + (img - NB) * NPIX);
    float acc[9];
#pragma unroll
    for (int o = 0; o < 9; o++) acc[o] = 0.0f;
#pragma unroll
    for (int ky = 0; ky < 5; ky++) {
        int iy = y + ky - 2;
        if ((unsigned)iy >= NN) continue;
#pragma unroll
        for (int kx = 0; kx < 5; kx++) {
            int ix = x + kx - 2;
            if ((unsigned)ix >= NN) continue;
            float v = __ldg(src + iy * NN + ix);
#pragma unroll
            for (int o = 0; o < 9; o++)
                acc[o] = fmaf(v, __ldg(w1 + o * 25 + ky * 5 + kx), acc[o]);
        }
    }
    {
        float a = acc[0];
        float n = sqrtf(a * a + 1e-12f);
        d_h1[img][0][p] = a * (n / (n + 1e-12f));
    }
#pragma unroll
    for (int g = 0; g < 4; g++) {
        int s = 1 + 2 * g;
        float a = acc[s], b = acc[s + 1];
        float n = sqrtf(a * a + b * b + 1e-12f);
        float sc = n / (n + 1e-12f);
        d_h1[img][s][p] = a * sc;
        d_h1[img][s + 1][p] = b * sc;
    }
}

// ---------------- conv2 + norm_relu (FIELDS2) + features --------------------
__global__ void k_conv2(const float* __restrict__ w2) {
    int img = blockIdx.y;
    int p = blockIdx.x * blockDim.x + threadIdx.x;
    if (p >= NPIX) return;
    int y = p / NN, x = p % NN;
    float acc[3] = {0.f, 0.f, 0.f};
    for (int ci = 0; ci < 9; ci++) {
        const float* hp = d_h1[img][ci];
#pragma unroll
        for (int ky = 0; ky < 5; ky++) {
            int iy = y + ky - 2;
            if ((unsigned)iy >= NN) continue;
#pragma unroll
            for (int kx = 0; kx < 5; kx++) {
                int ix = x + kx - 2;
                if ((unsigned)ix >= NN) continue;
                float v = hp[iy * NN + ix];
#pragma unroll
                for (int o = 0; o < 3; o++)
                    acc[o] = fmaf(v, __ldg(w2 + ((o * 9 + ci) * 5 + ky) * 5 + kx), acc[o]);
            }
        }
    }
    float o0, o1, o2;
    {
        float a = acc[0];
        float n = sqrtf(a * a + 1e-12f);
        o0 = a * (n / (n + 1e-12f));
    }
    {
        float a = acc[1], b = acc[2];
        float n = sqrtf(a * a + b * b + 1e-12f);
        float sc = n / (n + 1e-12f);
        o1 = a * sc; o2 = b * sc;
    }
    d_feat[img][0][p] = fabsf(o0);
    d_feat[img][1][p] = sqrtf(o1 * o1 + o2 * o2 + 1e-12f);
}

__device__ __forceinline__ float samp(const float* __restrict__ im, float yf, float xf) {
    if (yf < 0.f || yf >= 100.f || xf < 0.f || xf >= 100.f) return 0.f;
    int yc = (int)yf, xc = (int)xf;
    return im[yc * NN + xc];
}

// Complex accumulate with explicit twiddle (2 complex vals per float4)
#define CACC4(Tr, Ti, f4, twr, twi) \
    Tr[2*q]   = fmaf((f4).x, twr, Tr[2*q]);   Tr[2*q]   = fmaf(-(f4).y, twi, Tr[2*q]); \
    Ti[2*q]   = fmaf((f4).x, twi, Ti[2*q]);   Ti[2*q]   = fmaf( (f4).y, twr, Ti[2*q]); \
    Tr[2*q+1] = fmaf((f4).z, twr, Tr[2*q+1]); Tr[2*q+1] = fmaf(-(f4).w, twi, Tr[2*q+1]); \
    Ti[2*q+1] = fmaf((f4).z, twi, Ti[2*q+1]); Ti[2*q+1] = fmaf( (f4).w, twr, Ti[2*q+1]);

// Real-input accumulate: U += v * ws (v real float4, 4 lanes)
#define RACCR(Ur, Ui, f4) \
    Ur[4*q+0] = fmaf((f4).x, wsr, Ur[4*q+0]); Ui[4*q+0] = fmaf((f4).x, wsi, Ui[4*q+0]); \
    Ur[4*q+1] = fmaf((f4).y, wsr, Ur[4*q+1]); Ui[4*q+1] = fmaf((f4).y, wsi, Ui[4*q+1]); \
    Ur[4*q+2] = fmaf((f4).z, wsr, Ur[4*q+2]); Ui[4*q+2] = fmaf((f4).z, wsi, Ui[4*q+2]); \
    Ur[4*q+3] = fmaf((f4).w, wsr, Ur[4*q+3]); Ui[4*q+3] = fmaf((f4).w, wsi, Ui[4*q+3]);

// ---------------- rotate (fused) + row DFT, RADIX-4 (real input) ------------
// x = 4s+c. U_c = sum_s rot[4s+c] W^s (real*complex, shared stream W = w^4),
// T_c = w^c U_c, w = e^{-i pi u/100}.  G[u+50j] = sum_c (-i)^{jc} T_c.
// Store j=0 (kx=u), j=1 (kx=u+50), and j=2 only for u=0 (kx=100).
__global__ void __launch_bounds__(256) k_rot_rowdft() {
    __shared__ __align__(16) float rotT[NN * 104];   // [x][y], pitch 104, y 100..103 zeroed
    int bid = blockIdx.x;
    int tid = threadIdx.x;
    const float* src;
    bool ident;
    float ct = 1.f, st = 0.f;
    if (bid < NLIGH) {
        int c = bid & 1;
        int r = (bid >> 1) % RRH;
        int b = bid / (2 * RRH);
        src = d_feat[NB + b][c];
        double th = -3.14159265358979323846 + (double)r * (6.283185307179586477 / 360.0);
        ct = (float)cos(th); st = (float)sin(th);
        ident = false;
    } else {
        int i = bid - NLIGH;
        src = d_feat[i >> 1][i & 1];
        ident = true;
    }
    // zero y-pad columns 100..103 for every x row
    for (int p = tid; p < NN * 4; p += 256) {
        rotT[(p >> 2) * 104 + 100 + (p & 3)] = 0.f;
    }
    for (int p = tid; p < NPIX; p += blockDim.x) {
        int i = p / NN, j = p % NN;
        float val;
        if (ident) {
            val = src[p];
        } else {
            float xs = (float)j - 49.5f, ys = (float)i - 49.5f;
            float xq = ct * xs + st * ys + 49.5f;
            float yq = -st * xs + ct * ys + 49.5f;
            float x0f = floorf(xq), y0f = floorf(yq);
            float wx = xq - x0f, wy = yq - y0f;
            val = samp(src, y0f, x0f) * (1.f - wy) * (1.f - wx)
                + samp(src, y0f, x0f + 1.f) * (1.f - wy) * wx
                + samp(src, y0f + 1.f, x0f) * wy * (1.f - wx)
                + samp(src, y0f + 1.f, x0f + 1.f) * wy * wx;
        }
        rotT[j * 104 + i] = val;   // transposed: row = x, col = y
    }
    __syncthreads();
    // 650 tasks = 13 y-groups of 8 x 50 u (u fastest)
    for (int task = tid; task < 650; task += 256) {
        int u = task % 50;
        int y0 = (task / 50) * 8;
        float w1r, w1i;
        sincosf(-3.14159265358979f * (float)u * 0.01f, &w1i, &w1r);     // w
        float w2r = w1r * w1r - w1i * w1i, w2i = 2.f * w1r * w1i;       // w^2
        float w3r = w2r * w1r - w2i * w1i, w3i = w2r * w1i + w2i * w1r; // w^3
        int uw = (u > 25) ? u - 50 : u;
        float Wr, Wi;
        sincosf(-6.28318530717959f * (float)uw * 0.02f, &Wi, &Wr);      // W = w^4
        float wsr = 1.f, wsi = 0.f;
        float U0r[8], U0i[8], U1r[8], U1i[8], U2r[8], U2i[8], U3r[8], U3i[8];
#pragma unroll
        for (int i = 0; i < 8; i++) { U0r[i]=U0i[i]=U1r[i]=U1i[i]=U2r[i]=U2i[i]=U3r[i]=U3i[i]=0.f; }
        for (int s = 0; s < 25; s++) {
            const float4* p0 = reinterpret_cast<const float4*>(&rotT[(4*s    ) * 104 + y0]);
            const float4* p1 = reinterpret_cast<const float4*>(&rotT[(4*s + 1) * 104 + y0]);
            const float4* p2 = reinterpret_cast<const float4*>(&rotT[(4*s + 2) * 104 + y0]);
            const float4* p3 = reinterpret_cast<const float4*>(&rotT[(4*s + 3) * 104 + y0]);
#pragma unroll
            for (int q = 0; q < 2; q++) {
                float4 v0 = p0[q]; RACCR(U0r, U0i, v0)
                float4 v1 = p1[q]; RACCR(U1r, U1i, v1)
                float4 v2 = p2[q]; RACCR(U2r, U2i, v2)
                float4 v3 = p3[q]; RACCR(U3r, U3i, v3)
            }
            float nsr = wsr * Wr - wsi * Wi;
            float nsi = wsr * Wi + wsi * Wr;
            wsr = nsr; wsi = nsi;
        }
#pragma unroll
        for (int i = 0; i < 8; i++) {
            int y = y0 + i;
            if (y >= NN) continue;
            float T0r = U0r[i],                      T0i = U0i[i];
            float T1r = w1r * U1r[i] - w1i * U1i[i], T1i = w1r * U1i[i] + w1i * U1r[i];
            float T2r = w2r * U2r[i] - w2i * U2i[i], T2i = w2r * U2i[i] + w2i * U2r[i];
            float T3r = w3r * U3r[i] - w3i * U3i[i], T3i = w3r * U3i[i] + w3i * U3r[i];
            float acr = T0r + T2r, aci = T0i + T2i;
            float amr = T0r - T2r, ami = T0i - T2i;
            float bdr = T1r + T3r, bdi = T1i + T3i;
            float bmr = T1r - T3r, bmi = T1i - T3i;
            d_G[bid][y][u]      = make_float2(acr + bdr, aci + bdi);            // j=0
            d_G[bid][y][u + 50] = make_float2(amr + bmi, ami - bmr);            // j=1: am - i*bm
            if (u == 0)
                d_G[bid][y][100] = make_float2(acr - bdr, aci - bdi);           // j=2
        }
    }
}

// ---------------- column DFT, RADIX-8 (forward) -----------------------------
// y = 8t+c (GT zero-padded to 104 rows). S_c = sum_t G[8t+c] W^t, W = e^{-2pi i u/25}.
// T_c = w^c S_c, w = e^{-i pi u/100}. F[u+25j] = sum_c T_c e^{-i pi c j/4}.
__global__ void __launch_bounds__(256) k_coldft() {
    __shared__ __align__(16) float2 GT[104][56];
    int img = blockIdx.x >> 1;
    int half = blockIdx.x & 1;
    int kxg0 = half * 52;
    int width = half ? 49 : 52;
    int tid = threadIdx.x;
    for (int t = tid; t < 104 * 56; t += 256) {
        int y = t / 56, kxl = t % 56;
        float2 v = make_float2(0.f, 0.f);
        if (y < NN && kxl < width) v = d_G[img][y][kxg0 + kxl];
        GT[y][kxl] = v;
    }
    __syncthreads();
    // 650 tasks = 26 kx-groups of 2 x 25 u (u fastest)
    for (int task = tid; task < 650; task += 256) {
        int u = task % 25;
        int kxl0 = (task / 25) * 2;
        int uw = (u > 12) ? u - 25 : u;
        float Wi_, Wr_;
        sincosf(-6.28318530717959f * (float)uw * 0.04f, &Wi_, &Wr_);   // W = e^{-2pi i u/25}
        float wsr = 1.f, wsi = 0.f;
        float S0r[2], S0i[2], S1r[2], S1i[2], S2r[2], S2i[2], S3r[2], S3i[2];
        float S4r[2], S4i[2], S5r[2], S5i[2], S6r[2], S6i[2], S7r[2], S7i[2];
#pragma unroll
        for (int j = 0; j < 2; j++) {
            S0r[j]=S0i[j]=S1r[j]=S1i[j]=S2r[j]=S2i[j]=S3r[j]=S3i[j]=0.f;
            S4r[j]=S4i[j]=S5r[j]=S5i[j]=S6r[j]=S6i[j]=S7r[j]=S7i[j]=0.f;
        }
        for (int t = 0; t < 13; t++) {
            const int q = 0;
            float4 e0 = *reinterpret_cast<const float4*>(&GT[8*t    ][kxl0]); CACC4(S0r, S0i, e0, wsr, wsi)
            float4 e1 = *reinterpret_cast<const float4*>(&GT[8*t + 1][kxl0]); CACC4(S1r, S1i, e1, wsr, wsi)
            float4 e2 = *reinterpret_cast<const float4*>(&GT[8*t + 2][kxl0]); CACC4(S2r, S2i, e2, wsr, wsi)
            float4 e3 = *reinterpret_cast<const float4*>(&GT[8*t + 3][kxl0]); CACC4(S3r, S3i, e3, wsr, wsi)
            float4 e4 = *reinterpret_cast<const float4*>(&GT[8*t + 4][kxl0]); CACC4(S4r, S4i, e4, wsr, wsi)
            float4 e5 = *reinterpret_cast<const float4*>(&GT[8*t + 5][kxl0]); CACC4(S5r, S5i, e5, wsr, wsi)
            float4 e6 = *reinterpret_cast<const float4*>(&GT[8*t + 6][kxl0]); CACC4(S6r, S6i, e6, wsr, wsi)
            float4 e7 = *reinterpret_cast<const float4*>(&GT[8*t + 7][kxl0]); CACC4(S7r, S7i, e7, wsr, wsi)
            float nsr = wsr * Wr_ - wsi * Wi_;
            float nsi = wsr * Wi_ + wsi * Wr_;
            wsr = nsr; wsi = nsi;
        }
        float w1r_, w1i_, w2r_, w2i_;
        sincosf(-3.14159265358979f * (float)u * 0.01f, &w1i_, &w1r_);  // w
        sincosf(-3.14159265358979f * (float)u * 0.02f, &w2i_, &w2r_);  // w^2
        float w3r_ = w1r_*w2r_ - w1i_*w2i_, w3i_ = w1r_*w2i_ + w1i_*w2r_;
        float w4r_ = w2r_*w2r_ - w2i_*w2i_, w4i_ = 2.f*w2r_*w2i_;
        float w5r_ = w2r_*w3r_ - w2i_*w3i_, w5i_ = w2r_*w3i_ + w2i_*w3r_;
        float w6r_ = w3r_*w3r_ - w3i_*w3i_, w6i_ = 2.f*w3r_*w3i_;
        float w7r_ = w3r_*w4r_ - w3i_*w4i_, w7i_ = w3r_*w4i_ + w3i_*w4r_;
#pragma unroll
        for (int jj = 0; jj < 2; jj++) {
            int kxl = kxl0 + jj;
            if (kxl >= width) continue;
            int kx = kxg0 + kxl;
            float V1r = w1r_*S1r[jj] - w1i_*S1i[jj], V1i = w1r_*S1i[jj] + w1i_*S1r[jj];
            float V2r = w2r_*S2r[jj] - w2i_*S2i[jj], V2i = w2r_*S2i[jj] + w2i_*S2r[jj];
            float V3r = w3r_*S3r[jj] - w3i_*S3i[jj], V3i = w3r_*S3i[jj] + w3i_*S3r[jj];
            float V4r = w4r_*S4r[jj] - w4i_*S4i[jj], V4i = w4r_*S4i[jj] + w4i_*S4r[jj];
            float V5r = w5r_*S5r[jj] - w5i_*S5i[jj], V5i = w5r_*S5i[jj] + w5i_*S5r[jj];
            float V6r = w6r_*S6r[jj] - w6i_*S6i[jj], V6i = w6r_*S6i[jj] + w6i_*S6r[jj];
            float V7r = w7r_*S7r[jj] - w7i_*S7i[jj], V7i = w7r_*S7i[jj] + w7i_*S7r[jj];
            float acr = S0r[jj] + V4r, aci = S0i[jj] + V4i;
            float amr = S0r[jj] - V4r, ami = S0i[jj] - V4i;
            float bdr = V2r + V6r, bdi = V2i + V6i;
            float bmr = V2r - V6r, bmi = V2i - V6i;
            float E0r = acr + bdr, E0i = aci + bdi;
            float E2r = acr - bdr, E2i = aci - bdi;
            float E1r = amr + bmi, E1i = ami - bmr;       // am - i*bm (forward)
            float E3r = amr - bmi, E3i = ami + bmr;       // am + i*bm
            float pcr = V1r + V5r, pci = V1i + V5i;
            float pmr = V1r - V5r, pmi = V1i - V5i;
            float qdr = V3r + V7r, qdi = V3i + V7i;
            float qmr = V3r - V7r, qmi = V3i - V7i;
            float G0r = pcr + qdr, G0i = pci + qdi;
            float G2r = pcr - qdr, G2i = pci - qdi;
            float G1r = pmr + qmi, G1i = pmi - qmr;       // pm - i*qm
            float G3r = pmr - qmi, G3i = pmi + qmr;       // pm + i*qm
            float O0r = G0r,                O0i = G0i;
            float O1r = RT2 * (G1r + G1i),  O1i = RT2 * (G1i - G1r);    // e^{-i pi/4} G1
            float O2r = G2i,                O2i = -G2r;                 // -i G2
            float O3r = RT2 * (G3i - G3r),  O3i = -RT2 * (G3r + G3i);   // e^{-3i pi/4} G3
            d_F[img][kx][u]       = make_float2(E0r + O0r, E0i + O0i);
            d_F[img][kx][u + 100] = make_float2(E0r - O0r, E0i - O0i);
            d_F[img][kx][u + 25]  = make_float2(E1r + O1r, E1i + O1i);
            d_F[img][kx][u + 125] = make_float2(E1r - O1r, E1i - O1i);
            d_F[img][kx][u + 50]  = make_float2(E2r + O2r, E2i + O2i);
            d_F[img][kx][u + 150] = make_float2(E2r - O2r, E2i - O2i);
            d_F[img][kx][u + 75]  = make_float2(E3r + O3r, E3i + O3i);
            d_F[img][kx][u + 175] = make_float2(E3r - O3r, E3i - O3i);
        }
    }
}

// ---------------- combine spectra + inverse ky (RADIX-8) --------------------
__global__ void __launch_bounds__(320) k_combine_invy(const float* __restrict__ wb,
        const float* __restrict__ wc1, const float* __restrict__ wc2,
        const float* __restrict__ wk) {
    __shared__ __align__(16) float2 sfs[SS][24];
    __shared__ float2 ph[304];
    int chunk = blockIdx.x % 5;
    int imgH = blockIdx.x / 5;
    int b = imgH / RR;
    int r = imgH % RR;
    bool flip = (r >= RRH);
    int rb180 = flip ? r - RRH : r;
    int kxg0 = chunk * 24;
    int width = (KXN - kxg0 < 24) ? (KXN - kxg0) : 24;
    int tid = threadIdx.x;
    float w0 = *wb, w1v = *wc1, w2v = *wc2, w3v = *wk;
    int imgL0 = (b * RRH + rb180) * 2, imgL1 = imgL0 + 1;
    int imgR0 = NLIGH + b * 2, imgR1 = imgR0 + 1;
    if (flip) {
        for (int s = tid; s < 301; s += 320) {
            float pr, pi_;
            sincosf(3.14159265358979f * 0.01f * (float)s, &pi_, &pr);
            if (s & 1) { pr = -pr; pi_ = -pi_; }
            ph[s] = make_float2(pr, pi_);
        }
        __syncthreads();
    }
    for (int e = tid; e < SS * 24; e += 320) {
        int ky = e % SS, kxl = e / SS;
        float2 v = make_float2(0.f, 0.f);
        if (kxl < width) {
            int kx = kxg0 + kxl;
            float2 lb = d_F[imgL0][kx][ky];
            float2 lB = d_F[imgL1][kx][ky];
            if (flip) {
                float2 p = ph[kx + ky];
                float t;
                t    = p.x * lb.x + p.y * lb.y;
                lb.y = p.y * lb.x - p.x * lb.y;
                lb.x = t;
                t    = p.x * lB.x + p.y * lB.y;
                lB.y = p.y * lB.x - p.x * lB.y;
                lB.x = t;
            }
            float2 rb = d_F[imgR0][kx][ky];
            float2 rB = d_F[imgR1][kx][ky];
            float ur = w0 * lb.x + w1v * lB.x, ui = w0 * lb.y + w1v * lB.y;
            float vr = w2v * lb.x - w3v * lB.x, vi = w2v * lb.y - w3v * lB.y;
            v.x = rb.x * ur + rb.y * ui + rB.x * vr + rB.y * vi;
            v.y = rb.x * ui - rb.y * ur + rB.x * vi - rB.y * vr;
        }
        sfs[ky][kxl] = v;
    }
    __syncthreads();
    for (int task = tid; task < 300; task += 320) {
        int v = task % 25;
        int kxl0 = (task / 25) * 2;
        int vw = (v > 12) ? v - 25 : v;
        float Wi_, Wr_;
        sincosf(6.28318530717959f * (float)vw * 0.04f, &Wi_, &Wr_);
        float wsr = 1.f, wsi = 0.f;
        float S0r[2], S0i[2], S1r[2], S1i[2], S2r[2], S2i[2], S3r[2], S3i[2];
        float S4r[2], S4i[2], S5r[2], S5i[2], S6r[2], S6i[2], S7r[2], S7i[2];
#pragma unroll
        for (int j = 0; j < 2; j++) {
            S0r[j]=S0i[j]=S1r[j]=S1i[j]=S2r[j]=S2i[j]=S3r[j]=S3i[j]=0.f;
            S4r[j]=S4i[j]=S5r[j]=S5i[j]=S6r[j]=S6i[j]=S7r[j]=S7i[j]=0.f;
        }
        for (int t = 0; t < 25; t++) {
            const int q = 0;
            float4 e0 = *reinterpret_cast<const float4*>(&sfs[8*t    ][kxl0]); CACC4(S0r, S0i, e0, wsr, wsi)
            float4 e1 = *reinterpret_cast<const float4*>(&sfs[8*t + 1][kxl0]); CACC4(S1r, S1i, e1, wsr, wsi)
            float4 e2 = *reinterpret_cast<const float4*>(&sfs[8*t + 2][kxl0]); CACC4(S2r, S2i, e2, wsr, wsi)
            float4 e3 = *reinterpret_cast<const float4*>(&sfs[8*t + 3][kxl0]); CACC4(S3r, S3i, e3, wsr, wsi)
            float4 e4 = *reinterpret_cast<const float4*>(&sfs[8*t + 4][kxl0]); CACC4(S4r, S4i, e4, wsr, wsi)
            float4 e5 = *reinterpret_cast<const float4*>(&sfs[8*t + 5][kxl0]); CACC4(S5r, S5i, e5, wsr, wsi)
            float4 e6 = *reinterpret_cast<const float4*>(&sfs[8*t + 6][kxl0]); CACC4(S6r, S6i, e6, wsr, wsi)
            float4 e7 = *reinterpret_cast<const float4*>(&sfs[8*t + 7][kxl0]); CACC4(S7r, S7i, e7, wsr, wsi)
            float nsr = wsr * Wr_ - wsi * Wi_;
            float nsi = wsr * Wi_ + wsi * Wr_;
            wsr = nsr; wsi = nsi;
        }
        float w1r_, w1i_, w2r_, w2i_;
        sincosf(3.14159265358979f * (float)v * 0.01f, &w1i_, &w1r_);
        sincosf(3.14159265358979f * (float)v * 0.02f, &w2i_, &w2r_);
        float w3r_ = w1r_*w2r_ - w1i_*w2i_, w3i_ = w1r_*w2i_ + w1i_*w2r_;
        float w4r_ = w2r_*w2r_ - w2i_*w2i_, w4i_ = 2.f*w2r_*w2i_;
        float w5r_ = w2r_*w3r_ - w2i_*w3i_, w5i_ = w2r_*w3i_ + w2i_*w3r_;
        float w6r_ = w3r_*w3r_ - w3i_*w3i_, w6i_ = 2.f*w3r_*w3i_;
        float w7r_ = w3r_*w4r_ - w3i_*w4i_, w7i_ = w3r_*w4i_ + w3i_*w4r_;
#pragma unroll
        for (int jj = 0; jj < 2; jj++) {
            int kxl = kxl0 + jj;
            if (kxl >= width) continue;
            int kx = kxg0 + kxl;
            float V1r = w1r_*S1r[jj] - w1i_*S1i[jj], V1i = w1r_*S1i[jj] + w1i_*S1r[jj];
            float V2r = w2r_*S2r[jj] - w2i_*S2i[jj], V2i = w2r_*S2i[jj] + w2i_*S2r[jj];
            float V3r = w3r_*S3r[jj] - w3i_*S3i[jj], V3i = w3r_*S3i[jj] + w3i_*S3r[jj];
            float V4r = w4r_*S4r[jj] - w4i_*S4i[jj], V4i = w4r_*S4i[jj] + w4i_*S4r[jj];
            float V5r = w5r_*S5r[jj] - w5i_*S5i[jj], V5i = w5r_*S5i[jj] + w5i_*S5r[jj];
            float V6r = w6r_*S6r[jj] - w6i_*S6i[jj], V6i = w6r_*S6i[jj] + w6i_*S6r[jj];
            float V7r = w7r_*S7r[jj] - w7i_*S7i[jj], V7i = w7r_*S7i[jj] + w7i_*S7r[jj];
            float acr = S0r[jj] + V4r, aci = S0i[jj] + V4i;
            float amr = S0r[jj] - V4r, ami = S0i[jj] - V4i;
            float bdr = V2r + V6r, bdi = V2i + V6i;
            float bmr = V2r - V6r, bmi = V2i - V6i;
            float E0r = acr + bdr, E0i = aci + bdi;
            float E2r = acr - bdr, E2i = aci - bdi;
            float E1r = amr - bmi, E1i = ami + bmr;
            float E3r = amr + bmi, E3i = ami - bmr;
            float pcr = V1r + V5r, pci = V1i + V5i;
            float pmr = V1r - V5r, pmi = V1i - V5i;
            float qdr = V3r + V7r, qdi = V3i + V7i;
            float qmr = V3r - V7r, qmi = V3i - V7i;
            float G0r = pcr + qdr, G0i = pci + qdi;
            float G2r = pcr - qdr, G2i = pci - qdi;
            float G1r = pmr - qmi, G1i = pmi + qmr;
            float G3r = pmr + qmi, G3i = pmi - qmr;
            float O0r = G0r,               O0i = G0i;
            float O1r = RT2 * (G1r - G1i), O1i = RT2 * (G1r + G1i);
            float O2r = -G2i,              O2i = G2r;
            float O3r = -RT2 * (G3r + G3i), O3i = RT2 * (G3r - G3i);
            d_H[imgH][kx][v]       = make_float2(E0r + O0r, E0i + O0i);
            d_H[imgH][kx][v + 100] = make_float2(E0r - O0r, E0i - O0i);
            d_H[imgH][kx][v + 25]  = make_float2(E1r + O1r, E1i + O1i);
            d_H[imgH][kx][v + 125] = make_float2(E1r - O1r, E1i - O1i);
            d_H[imgH][kx][v + 50]  = make_float2(E2r + O2r, E2i + O2i);
            d_H[imgH][kx][v + 150] = make_float2(E2r - O2r, E2i - O2i);
            d_H[imgH][kx][v + 75]  = make_float2(E3r + O3r, E3i + O3i);
            d_H[imgH][kx][v + 175] = make_float2(E3r - O3r, E3i - O3i);
        }
    }
}

// ---------------- inverse kx (real, RADIX-8) + reduce -----------------------
__global__ void __launch_bounds__(256) k_invx_reduce(const int* __restrict__ gtr,
                                                     const int* __restrict__ gtt) {
    __shared__ __align__(16) float2 HT[104][20];
    __shared__ float red[256];
    int yc = blockIdx.x % 10;
    int imgH = blockIdx.x / 10;
    int b = imgH / RR, r = imgH % RR;
    int ybase = yc * 20;
    int tid = threadIdx.x;
    for (int e = tid; e < 104 * 20; e += 256) {
        int kx = e / 20, yl = e % 20;
        float2 val = make_float2(0.f, 0.f);
        if (kx < KXN) {
            val = d_H[imgH][kx][ybase + yl];
            if (kx == 0 || kx == 100) { val.x *= 0.5f; val.y *= 0.5f; }
        }
        HT[kx][yl] = val;
    }
    __syncthreads();
    int gr = gtr[b], t0 = gtt[2 * b], t1 = gtt[2 * b + 1];
    const float inv = 1.0f / 40000.0f;
    float lmax = -3.4e38f;
    for (int task = tid; task < 250; task += 256) {
        int v = task % 25;
        int y0 = (task / 25) * 2;
        int vw = (v > 12) ? v - 25 : v;
        float Wi_, Wr_;
        sincosf(6.28318530717959f * (float)vw * 0.04f, &Wi_, &Wr_);
        float wsr = 1.f, wsi = 0.f;
        float Z0r[2], Z0i[2], Z1r[2], Z1i[2], Z2r[2], Z2i[2], Z3r[2], Z3i[2];
        float Z4r[2], Z4i[2], Z5r[2], Z5i[2], Z6r[2], Z6i[2], Z7r[2], Z7i[2];
#pragma unroll
        for (int j = 0; j < 2; j++) {
            Z0r[j]=Z0i[j]=Z1r[j]=Z1i[j]=Z2r[j]=Z2i[j]=Z3r[j]=Z3i[j]=0.f;
            Z4r[j]=Z4i[j]=Z5r[j]=Z5i[j]=Z6r[j]=Z6i[j]=Z7r[j]=Z7i[j]=0.f;
        }
        for (int t = 0; t < 13; t++) {
            const int q = 0;
            float4 h0 = *reinterpret_cast<const float4*>(&HT[8*t    ][y0]); CACC4(Z0r, Z0i, h0, wsr, wsi)
            float4 h1 = *reinterpret_cast<const float4*>(&HT[8*t + 1][y0]); CACC4(Z1r, Z1i, h1, wsr, wsi)
            float4 h2 = *reinterpret_cast<const float4*>(&HT[8*t + 2][y0]); CACC4(Z2r, Z2i, h2, wsr, wsi)
            float4 h3 = *reinterpret_cast<const float4*>(&HT[8*t + 3][y0]); CACC4(Z3r, Z3i, h3, wsr, wsi)
            float4 h4 = *reinterpret_cast<const float4*>(&HT[8*t + 4][y0]); CACC4(Z4r, Z4i, h4, wsr, wsi)
            float4 h5 = *reinterpret_cast<const float4*>(&HT[8*t + 5][y0]); CACC4(Z5r, Z5i, h5, wsr, wsi)
            float4 h6 = *reinterpret_cast<const float4*>(&HT[8*t + 6][y0]); CACC4(Z6r, Z6i, h6, wsr, wsi)
            float4 h7 = *reinterpret_cast<const float4*>(&HT[8*t + 7][y0]); CACC4(Z7r, Z7i, h7, wsr, wsi)
            float nsr = wsr * Wr_ - wsi * Wi_;
            float nsi = wsr * Wi_ + wsi * Wr_;
            wsr = nsr; wsi = nsi;
        }
        float w1r_, w1i_, w2r_, w2i_;
        sincosf(3.14159265358979f * (float)v * 0.01f, &w1i_, &w1r_);
        sincosf(3.14159265358979f * (float)v * 0.02f, &w2i_, &w2r_);
        float w3r_ = w1r_*w2r_ - w1i_*w2i_, w3i_ = w1r_*w2i_ + w1i_*w2r_;
        float w4r_ = w2r_*w2r_ - w2i_*w2i_, w4i_ = 2.f*w2r_*w2i_;
        float w5r_ = w2r_*w3r_ - w2i_*w3i_, w5i_ = w2r_*w3i_ + w2i_*w3r_;
        float w6r_ = w3r_*w3r_ - w3i_*w3i_, w6i_ = 2.f*w3r_*w3i_;
        float w7r_ = w3r_*w4r_ - w3i_*w4i_, w7i_ = w3r_*w4i_ + w3i_*w4r_;
#pragma unroll
        for (int i = 0; i < 2; i++) {
            float V1r = w1r_*Z1r[i] - w1i_*Z1i[i], V1i = w1r_*Z1i[i] + w1i_*Z1r[i];
            float V2r = w2r_*Z2r[i] - w2i_*Z2i[i], V2i = w2r_*Z2i[i] + w2i_*Z2r[i];
            float V3r = w3r_*Z3r[i] - w3i_*Z3i[i], V3i = w3r_*Z3i[i] + w3i_*Z3r[i];
            float V4r = w4r_*Z4r[i] - w4i_*Z4i[i], V4i = w4r_*Z4i[i] + w4i_*Z4r[i];
            float V5r = w5r_*Z5r[i] - w5i_*Z5i[i], V5i = w5r_*Z5i[i] + w5i_*Z5r[i];
            float V6r = w6r_*Z6r[i] - w6i_*Z6i[i], V6i = w6r_*Z6i[i] + w6i_*Z6r[i];
            float V7r = w7r_*Z7r[i] - w7i_*Z7i[i], V7i = w7r_*Z7i[i] + w7i_*Z7r[i];
            float acr = Z0r[i] + V4r, aci = Z0i[i] + V4i;
            float amr = Z0r[i] - V4r, ami = Z0i[i] - V4i;
            float bdr = V2r + V6r, bdi = V2i + V6i;
            float bmr = V2r - V6r, bmi = V2i - V6i;
            float E0r = acr + bdr;
            float E2r = acr - bdr;
            float E1r = amr - bmi;
            float E3r = amr + bmi;
            float pcr = V1r + V5r, pci = V1i + V5i;
            float pmr = V1r - V5r, pmi = V1i - V5i;
            float qdr = V3r + V7r, qdi = V3i + V7i;
            float qmr = V3r - V7r, qmi = V3i - V7i;
            float G0r = pcr + qdr;
            float G2i = pci - qdi;
            float G1r = pmr - qmi, G1i = pmi + qmr;
            float G3r = pmr + qmi, G3i = pmi - qmr;
            float O0r = G0r;
            float O1r = RT2 * (G1r - G1i);
            float O2r = -G2i;
            float O3r = -RT2 * (G3r + G3i);
            float sc = 2.f * inv;
            float s[8];
            s[0] = (E0r + O0r) * sc;  s[4] = (E0r - O0r) * sc;
            s[1] = (E1r + O1r) * sc;  s[5] = (E1r - O1r) * sc;
            s[2] = (E2r + O2r) * sc;  s[6] = (E2r - O2r) * sc;
            s[3] = (E3r + O3r) * sc;  s[7] = (E3r - O3r) * sc;
#pragma unroll
            for (int j = 0; j < 8; j++) lmax = fmaxf(lmax, s[j]);
            int y = ybase + y0 + i;
            if (r == gr && y == t0) {
#pragma unroll
                for (int j = 0; j < 8; j++)
                    if (v + 25 * j == t1) d_pos[b] = s[j];
            }
        }
    }
    red[tid] = lmax;
    __syncthreads();
    for (int s2 = 128; s2 > 0; s2 >>= 1) {
        if (tid < s2) red[tid] = fmaxf(red[tid], red[tid + s2]);
        __syncthreads();
    }
    if (tid == 0) atomicMax(&d_best[b], fenc(red[0]));
}

__global__ void k_final(float* __restrict__ out) {
    if (threadIdx.x == 0) {
        float lp = 0.f, ln = 0.f;
        for (int b = 0; b < NB; b++) {
            float p = d_pos[b];
            lp += p + p * p;
            float m = fdec(d_best[b]);
            ln += -m + m * m;
        }
        out[0] = lp / (float)NB;
        out[1] = ln / (float)NB;
    }
}

extern "C" void kernel_launch(void* const* d_in, const int* in_sizes, int n_in,
                              void* d_out, int out_size) {
    const float* rec = (const float*)d_in[0];
    const float* lig = (const float*)d_in[1];
    const float* w1 = (const float*)d_in[2];
    const float* w2 = (const float*)d_in[3];
    const float* wb = (const float*)d_in[4];
    const float* wc1 = (const float*)d_in[5];
    const float* wc2 = (const float*)d_in[6];
    const float* wk = (const float*)d_in[7];
    const int* gtr = (const int*)d_in[8];
    const int* gtt = (const int*)d_in[9];
    float* out = (float*)d_out;

    k_init<<<1, 32>>>();
    dim3 gconv((NPIX + 255) / 256, 4);
    k_conv1<<<gconv, 256>>>(rec, lig, w1);
    k_conv2<<<gconv, 256>>>(w2);
    k_rot_rowdft<<<NIMGH, 256>>>();
    k_coldft<<<NIMGH * 2, 256>>>();
    k_combine_invy<<<NB * RR * 5, 320>>>(wb, wc1, wc2, wk);
    k_invx_reduce<<<NB * RR * 10, 256>>>(gtr, gtt);
    k_final<<<1, 32>>>(out);
}